// round 12
// baseline (speedup 1.0000x reference)
#include <cuda_runtime.h>
#include <math.h>

#define NG     320
#define NS1    (NG*NG)
#define NSHOT  2
#define NSRC   8
#define NREC   96
#define NT     160
#define PML_W  20
#define NBLK   256          // 128 tiles x 2 shots
#define TPB    400
#define TILE_R 20
#define TILE_C 40
#define TCB    8
#define TRB    16
#define SW     45           // velocity SMEM frame stride (44 used + pad), 24 rows
#define IDHF   0.25f
#define DTF    4.0e-4f

// Triple-buffered global stress. Velocity lives in registers/SMEM only.
__device__ float g_syy[3][NSHOT*NS1];
__device__ float g_sxy[3][NSHOT*NS1];
__device__ float g_sxx[3][NSHOT*NS1];
__device__ float g_recs[NT*NSHOT*NREC];

__device__ __align__(128) unsigned g_flag[NBLK*32];
__device__ __align__(128) unsigned g_count = 0;
__device__ __align__(128) volatile unsigned g_phase = 0;

__device__ __forceinline__ void gbar(unsigned target)
{
    __syncthreads();
    if (threadIdx.x == 0) {
        __threadfence();
        if (atomicAdd(&g_count, 1u) == NBLK - 1) {
            g_count = 0;
            __threadfence();
            g_phase = target;
        } else {
            while ((int)(g_phase - target) < 0) { }
        }
        __threadfence();
    }
    __syncthreads();
}

__device__ __forceinline__ unsigned ld_acq(const unsigned* p)
{
    unsigned v;
    asm volatile("ld.acquire.gpu.global.u32 %0, [%1];" : "=r"(v) : "l"(p) : "memory");
    return v;
}
__device__ __forceinline__ void red_add(unsigned* p)
{
    asm volatile("red.global.add.u32 [%0], %1;" :: "l"(p), "r"(1u) : "memory");
}

__device__ __forceinline__ float pml_b(int i)
{
    const double d0 = 3.0 * 1600.0 * log(1000.0) / (2.0 * PML_W * 4.0);
    double dd = 0.0;
    if (i < PML_W) {
        double a = (double)(PML_W - i) / PML_W;
        dd = d0 * a * a;
    } else if (i >= NG - PML_W) {
        double a = ((double)i - (NG - 1 - PML_W)) / PML_W;
        dd = d0 * a * a;
    }
    return (float)exp(-dd * 4.0e-4);
}

__device__ __forceinline__ float2 ld2(const float* __restrict__ p, int idx)
{
    return *reinterpret_cast<const float2*>(p + idx);
}
__device__ __forceinline__ void st2(float* __restrict__ p, int idx, float a, float b)
{
    *reinterpret_cast<float2*>(p + idx) = make_float2(a, b);
}

__global__ __launch_bounds__(TPB, 2) void sim_kernel(
    const float* __restrict__ lamb,
    const float* __restrict__ mu,
    const float* __restrict__ buoy,
    const float* __restrict__ amps,   // [NSHOT, NSRC, NT]
    const int*   __restrict__ sloc,   // [NSHOT, NSRC, 2]
    const int*   __restrict__ rloc,   // [NSHOT, NREC, 2]
    float* __restrict__ out)          // [NSHOT, NREC, NT-1]
{
    __shared__ float s_vy[24*SW];
    __shared__ float s_vx[24*SW];

    const int tid  = threadIdx.x;
    const int blk  = blockIdx.x;
    const int shot = blk & 1;
    const int tile = blk >> 1;
    const int by0 = (tile / TCB) * TILE_R;
    const int bx0 = (tile % TCB) * TILE_C;
    const int rr = tid / 20;
    const int pp = tid - rr * 20;
    const int cx = 2 * pp;
    const int y  = by0 + rr;
    const int x0 = bx0 + cx;
    const int base = shot * NS1;
    const int o = y * NG + x0;
    unsigned ph = g_phase;
    const unsigned F = g_flag[blk * 32];

    // all 8 same-shot torus neighbor flag indices
    int nboff[8];
    {
        const int dR[8] = {-1,-1,-1, 0, 0, 1, 1, 1};
        const int dC[8] = {-1, 0, 1,-1, 1,-1, 0, 1};
        int bR = tile / TCB, bC = tile % TCB;
#pragma unroll
        for (int i = 0; i < 8; i++) {
            int nR = (bR + dR[i] + TRB) % TRB;
            int nC = (bC + dC[i] + TCB) % TCB;
            nboff[i] = ((((nR * TCB + nC) << 1) | shot)) * 32;
        }
    }

    // neighbor mask from a tap bounding box in tile coords
    auto range_mask = [&](int rlo, int rhi, int clo, int chi) -> unsigned {
        unsigned m = 0;
        int rset = 1 | ((rlo < 0) ? 2 : 0) | ((rhi >= TILE_R) ? 4 : 0);
        int cset = 1 | ((clo < 0) ? 2 : 0) | ((chi >= TILE_C) ? 4 : 0);
        for (int a = 0; a < 3; a++) if ((rset >> a) & 1) {
            int dr = (a == 0) ? 0 : (a == 1) ? -1 : 1;
            for (int b = 0; b < 3; b++) if ((cset >> b) & 1) {
                int dc = (b == 0) ? 0 : (b == 1) ? -1 : 1;
                if (dr == 0 && dc == 0) continue;
                int idx = (dr + 1) * 3 + (dc + 1);
                if (idx > 4) idx--;
                m |= 1u << idx;
            }
        }
        return m;
    };

    auto poll = [&](unsigned pend, unsigned tgt) {
        while (pend) {
#pragma unroll
            for (int i = 0; i < 8; i++) {
                if (pend & (1u << i)) {
                    if ((int)(ld_acq(g_flag + nboff[i]) - tgt) >= 0) pend &= ~(1u << i);
                }
            }
        }
    };

    // ---- core wrapped global indices (float2 taps) ----
    const int ym1 = (y + NG - 1) % NG, ym2 = (y + NG - 2) % NG;
    const int yp1 = (y + 1) % NG,      yp2 = (y + 2) % NG;
    const int row  = y   * NG;
    const int rym1 = ym1 * NG, rym2 = ym2 * NG;
    const int ryp1 = yp1 * NG, ryp2 = yp2 * NG;
    const int xm2c = (x0 == 0)      ? NG - 2 : x0 - 2;
    const int xp2c = (x0 == NG - 2) ? 0      : x0 + 2;

    const float byv  = pml_b(y);
    const float bxv0 = pml_b(x0);
    const float bxv1 = pml_b(x0 + 1);
    const float2 bv2  = *reinterpret_cast<const float2*>(buoy + o);
    const float2 lam2 = *reinterpret_cast<const float2*>(lamb + o);
    const float2 mu2  = *reinterpret_cast<const float2*>(mu + o);
    const float l2m0 = lam2.x + 2.0f * mu2.x;
    const float l2m1 = lam2.y + 2.0f * mu2.y;
    const bool ybord = (y < 2 || y >= NG - 2);
    const float mk0 = (ybord || x0     < 2 || x0     >= NG - 2) ? 0.0f : 1.0f;
    const float mk1 = (ybord || x0 + 1 < 2 || x0 + 1 >= NG - 2) ? 0.0f : 1.0f;
    const int svc = (rr + 2) * SW + (cx + 2);    // own cell0 in SMEM vel frame
    const unsigned cmask = range_mask(rr - 2, rr + 2, cx - 2, cx + 3);

    unsigned smask = 0u;
#pragma unroll
    for (int s = 0; s < NSRC; s++) {
        int sy = sloc[(shot*NSRC + s)*2], sx = sloc[(shot*NSRC + s)*2 + 1];
        if (sy == y && sx == x0)     smask |= 1u << s;
        if (sy == y && sx == x0 + 1) smask |= 1u << (s + 8);
    }

    int rcode[8];
    int rcnt = 0;
    bool rovf = false;
    for (int r = 0; r < NREC; r++) {
        int e = shot * NREC + r;
        int ry = rloc[e*2], rx = rloc[e*2 + 1];
        if (ry == y && (rx == x0 || rx == x0 + 1)) {
            if (rcnt < 8) rcode[rcnt++] = e * 2 + (rx - x0);
            else rovf = true;
        }
    }

    // ---- ring: annulus 1..2 as 256 single cells on threads 0..255 ----
    const bool has_ring = (tid < 256);
    int i_o = 0, i_ym1 = 0, i_ym2 = 0, i_yp1 = 0, i_yp2 = 0;
    int i_xm1 = 0, i_xm2 = 0, i_xp1 = 0, i_xp2 = 0;
    int rvv = 0;
    float rbyv = 0, rbxv = 0, rbv = 0, rmk = 0;
    unsigned rsmask = 0u, rmask = 0u;
    if (has_ring) {
        int ty, tx;
        if (tid < 88)       { ty = -2 + tid / 44;          tx = -2 + tid % 44; }
        else if (tid < 176) { ty = 20 + (tid - 88) / 44;   tx = -2 + (tid - 88) % 44; }
        else if (tid < 216) { int j = tid - 176; ty = j / 2; tx = -2 + (j & 1); }
        else                { int j = tid - 216; ty = j / 2; tx = 40 + (j & 1); }
        rmask = range_mask(ty - 2, ty + 2, tx - 2, tx + 2);
        int gy = (by0 + ty + NG) % NG;
        int gx = (bx0 + tx + NG) % NG;
        int gro = gy * NG;
        i_o   = base + gro + gx;
        i_ym1 = base + ((gy + NG - 1) % NG) * NG + gx;
        i_ym2 = base + ((gy + NG - 2) % NG) * NG + gx;
        i_yp1 = base + ((gy + 1) % NG) * NG + gx;
        i_yp2 = base + ((gy + 2) % NG) * NG + gx;
        i_xm1 = base + gro + (gx + NG - 1) % NG;
        i_xm2 = base + gro + (gx + NG - 2) % NG;
        i_xp1 = base + gro + (gx + 1) % NG;
        i_xp2 = base + gro + (gx + 2) % NG;
        rvv = (ty + 2) * SW + (tx + 2);
        rbyv = pml_b(gy);
        rbxv = pml_b(gx);
        rbv  = buoy[gro + gx];
        rmk  = (gy < 2 || gy >= NG-2 || gx < 2 || gx >= NG-2) ? 0.0f : 1.0f;
#pragma unroll
        for (int s = 0; s < NSRC; s++)
            if (sloc[(shot*NSRC + s)*2] == gy && sloc[(shot*NSRC + s)*2 + 1] == gx)
                rsmask |= 1u << s;
    }

    // ---- persistent register state ----
    float vy0 = 0, vy1 = 0, vx0 = 0, vx1 = 0;
    float syy0 = 0, syy1 = 0, sxy0 = 0, sxy1 = 0, sxx0 = 0, sxx1 = 0;
    float cms[8] = {0,0,0,0,0,0,0,0};   // core CPML: msyyy,msxyx,msxxx,msxyy x2 cells
    float cmv[8] = {0,0,0,0,0,0,0,0};   // core CPML: mvyy,mvxx,mvyx,mvxy x2 cells
    float r_vy = 0, r_vx = 0;
    float rms[4] = {0,0,0,0};           // ring CPML (velocity)

    // init: zero SMEM vel frame + global stress buffer 2 core
    for (int i = tid; i < 24*SW; i += TPB) { s_vy[i] = 0.f; s_vx[i] = 0.f; }
    st2(g_syy[2], base + o, 0.f, 0.f);
    st2(g_sxy[2], base + o, 0.f, 0.f);
    st2(g_sxx[2], base + o, 0.f, 0.f);
    __syncthreads();
    if (tid == 0) { __threadfence(); red_add(&g_flag[blk * 32]); }   // flag = F+1

    const float C1 = 1.125f;
    const float C2 = -1.0f / 24.0f;

#pragma unroll 1
    for (int t = 0; t < NT; t++) {
        const unsigned tgt = F + 1u + (unsigned)t;
        const int p = (t + 2) % 3;     // read: stress(t-1)
        const int q = t % 3;           // write: stress(t)
        const float* __restrict__ Syy = g_syy[p];
        const float* __restrict__ Sxy = g_sxy[p];
        const float* __restrict__ Sxx = g_sxx[p];

        // ---- poll only the neighbors this thread's CORE taps touch ----
        if (cmask) poll(cmask, tgt);

        // ================= velocity: core pair =================
        {
            float d0, d1, m;

            float2 a_ym1 = ld2(Syy, base + rym1 + x0);
            float2 a_ym2 = ld2(Syy, base + rym2 + x0);
            float2 a_yp1 = ld2(Syy, base + ryp1 + x0);
            d0 = (C1*(syy0 - a_ym1.x) + C2*(a_yp1.x - a_ym2.x)) * IDHF;
            d1 = (C1*(syy1 - a_ym1.y) + C2*(a_yp1.y - a_ym2.y)) * IDHF;
            m = cms[0]; m = byv*m + (byv-1.0f)*d0; cms[0] = m;
            float ay0 = d0 + m;
            m = cms[4]; m = byv*m + (byv-1.0f)*d1; cms[4] = m;
            float ay1 = d1 + m;

            float2 u_xm = ld2(Sxy, base + row + xm2c);
            float2 u_xp = ld2(Sxy, base + row + xp2c);
            d0 = (C1*(sxy1 - sxy0) + C2*(u_xp.x - u_xm.y)) * IDHF;
            d1 = (C1*(u_xp.x - sxy1) + C2*(u_xp.y - sxy0)) * IDHF;
            m = cms[1]; m = bxv0*m + (bxv0-1.0f)*d0; cms[1] = m;
            ay0 += d0 + m;
            m = cms[5]; m = bxv1*m + (bxv1-1.0f)*d1; cms[5] = m;
            ay1 += d1 + m;

            vy0 += DTF * bv2.x * ay0;
            vy1 += DTF * bv2.y * ay1;

            float2 w_xm = ld2(Sxx, base + row + xm2c);
            float2 w_xp = ld2(Sxx, base + row + xp2c);
            d0 = (C1*(sxx0 - w_xm.y) + C2*(sxx1 - w_xm.x)) * IDHF;
            d1 = (C1*(sxx1 - sxx0) + C2*(w_xp.x - w_xm.y)) * IDHF;
            m = cms[2]; m = bxv0*m + (bxv0-1.0f)*d0; cms[2] = m;
            float ax0 = d0 + m;
            m = cms[6]; m = bxv1*m + (bxv1-1.0f)*d1; cms[6] = m;
            float ax1 = d1 + m;

            float2 s_yp1v = ld2(Sxy, base + ryp1 + x0);
            float2 s_yp2v = ld2(Sxy, base + ryp2 + x0);
            float2 s_ym1v = ld2(Sxy, base + rym1 + x0);
            d0 = (C1*(s_yp1v.x - sxy0) + C2*(s_yp2v.x - s_ym1v.x)) * IDHF;
            d1 = (C1*(s_yp1v.y - sxy1) + C2*(s_yp2v.y - s_ym1v.y)) * IDHF;
            m = cms[3]; m = byv*m + (byv-1.0f)*d0; cms[3] = m;
            ax0 += d0 + m;
            m = cms[7]; m = byv*m + (byv-1.0f)*d1; cms[7] = m;
            ax1 += d1 + m;

            vx0 += DTF * bv2.x * ax0;
            vx1 += DTF * bv2.y * ax1;

            if (smask) {
#pragma unroll
                for (int s = 0; s < NSRC; s++) {
                    float a = amps[(shot*NSRC + s)*NT + t];
                    if (smask & (1u << s))       vy0 += DTF * a * bv2.x;
                    if (smask & (1u << (s + 8))) vy1 += DTF * a * bv2.y;
                }
            }
            vy0 *= mk0; vy1 *= mk1;
            vx0 *= mk0; vx1 *= mk1;

            s_vy[svc]   = vy0;
            s_vy[svc+1] = vy1;
            s_vx[svc]   = vx0;
            s_vx[svc+1] = vx1;
        }

        // receivers (own registers only -> no ordering needed)
        if (rovf) {
            for (int r = 0; r < NREC; r++) {
                int e = shot * NREC + r;
                int ry = rloc[e*2], rx = rloc[e*2 + 1];
                if (ry == y && (rx == x0 || rx == x0 + 1))
                    g_recs[t*(NSHOT*NREC) + e] = (rx == x0) ? vy0 : vy1;
            }
        } else {
            for (int i = 0; i < rcnt; i++) {
                int e = rcode[i] >> 1;
                g_recs[t*(NSHOT*NREC) + e] = (rcode[i] & 1) ? vy1 : vy0;
            }
        }

        // ================= velocity: ring cell =================
        if (has_ring) {
            if (rmask) poll(rmask, tgt);
            float d, m;

            d = (C1*(Syy[i_o] - Syy[i_ym1]) + C2*(Syy[i_yp1] - Syy[i_ym2])) * IDHF;
            m = rms[0]; m = rbyv*m + (rbyv-1.0f)*d; rms[0] = m;
            float ay = d + m;

            d = (C1*(Sxy[i_xp1] - Sxy[i_o]) + C2*(Sxy[i_xp2] - Sxy[i_xm1])) * IDHF;
            m = rms[1]; m = rbxv*m + (rbxv-1.0f)*d; rms[1] = m;
            ay += d + m;

            r_vy += DTF * rbv * ay;

            d = (C1*(Sxx[i_o] - Sxx[i_xm1]) + C2*(Sxx[i_xp1] - Sxx[i_xm2])) * IDHF;
            m = rms[2]; m = rbxv*m + (rbxv-1.0f)*d; rms[2] = m;
            float ax = d + m;

            d = (C1*(Sxy[i_yp1] - Sxy[i_o]) + C2*(Sxy[i_yp2] - Sxy[i_ym1])) * IDHF;
            m = rms[3]; m = rbyv*m + (rbyv-1.0f)*d; rms[3] = m;
            ax += d + m;

            r_vx += DTF * rbv * ax;

            if (rsmask) {
#pragma unroll
                for (int s = 0; s < NSRC; s++)
                    if (rsmask & (1u << s))
                        r_vy += DTF * amps[(shot*NSRC + s)*NT + t] * rbv;
            }
            r_vy *= rmk;
            r_vx *= rmk;
            s_vy[rvv] = r_vy;
            s_vx[rvv] = r_vx;
        }

        __syncthreads();   // [V] velocity frame complete (and all polls done)

        // ================= stress: core (SMEM vel taps) =================
        {
            float d0, d1, m;

            d0 = (C1*(s_vy[svc+SW]   - vy0) + C2*(s_vy[svc+2*SW]   - s_vy[svc-SW])) * IDHF;
            d1 = (C1*(s_vy[svc+SW+1] - vy1) + C2*(s_vy[svc+2*SW+1] - s_vy[svc-SW+1])) * IDHF;
            m = cmv[0]; m = byv*m + (byv-1.0f)*d0; cmv[0] = m;
            float e10 = d0 + m;
            m = cmv[4]; m = byv*m + (byv-1.0f)*d1; cmv[4] = m;
            float e11 = d1 + m;

            float vxm1 = s_vx[svc-1], vxm2 = s_vx[svc-2];
            float vxp2 = s_vx[svc+2];
            d0 = (C1*(vx0 - vxm1) + C2*(vx1 - vxm2)) * IDHF;
            d1 = (C1*(vx1 - vx0) + C2*(vxp2 - vxm1)) * IDHF;
            m = cmv[1]; m = bxv0*m + (bxv0-1.0f)*d0; cmv[1] = m;
            float e20 = d0 + m;
            m = cmv[5]; m = bxv1*m + (bxv1-1.0f)*d1; cmv[5] = m;
            float e21 = d1 + m;

            syy0 = (syy0 + DTF*(l2m0*e10 + lam2.x*e20)) * mk0;
            syy1 = (syy1 + DTF*(l2m1*e11 + lam2.y*e21)) * mk1;
            sxx0 = (sxx0 + DTF*(l2m0*e20 + lam2.x*e10)) * mk0;
            sxx1 = (sxx1 + DTF*(l2m1*e21 + lam2.y*e11)) * mk1;

            float vym1 = s_vy[svc-1];
            float vyp2 = s_vy[svc+2], vyp3 = s_vy[svc+3];
            d0 = (C1*(vy1 - vy0) + C2*(vyp2 - vym1)) * IDHF;
            d1 = (C1*(vyp2 - vy1) + C2*(vyp3 - vy0)) * IDHF;
            m = cmv[2]; m = bxv0*m + (bxv0-1.0f)*d0; cmv[2] = m;
            float g0 = d0 + m;
            m = cmv[6]; m = bxv1*m + (bxv1-1.0f)*d1; cmv[6] = m;
            float g1 = d1 + m;

            d0 = (C1*(vx0 - s_vx[svc-SW])   + C2*(s_vx[svc+SW]   - s_vx[svc-2*SW])) * IDHF;
            d1 = (C1*(vx1 - s_vx[svc-SW+1]) + C2*(s_vx[svc+SW+1] - s_vx[svc-2*SW+1])) * IDHF;
            m = cmv[3]; m = byv*m + (byv-1.0f)*d0; cmv[3] = m;
            g0 += d0 + m;
            m = cmv[7]; m = byv*m + (byv-1.0f)*d1; cmv[7] = m;
            g1 += d1 + m;

            sxy0 = (sxy0 + DTF*mu2.x*g0) * mk0;
            sxy1 = (sxy1 + DTF*mu2.y*g1) * mk1;

            st2(g_syy[q], base + o, syy0, syy1);
            st2(g_sxy[q], base + o, sxy0, sxy1);
            st2(g_sxx[q], base + o, sxx0, sxx1);
        }

        // [S] publish step t
        __syncthreads();
        if (tid == 0) { __threadfence(); red_add(&g_flag[blk * 32]); }
    }

    // ---------------- finalize (needs all blocks' g_recs) ----------------
    gbar(ph + 1);
    const int gtid = blk * TPB + tid;
    const int total = NSHOT * NREC * (NT - 1);
    if (gtid < total) {
        int t = gtid % (NT - 1);
        int e = gtid / (NT - 1);
        out[e * (NT - 1) + t] = 0.5f * (g_recs[(t + 1)*(NSHOT*NREC) + e]
                                      + g_recs[t      *(NSHOT*NREC) + e]);
    }
}

extern "C" void kernel_launch(void* const* d_in, const int* in_sizes, int n_in,
                              void* d_out, int out_size)
{
    const float* lamb = (const float*)d_in[0];
    const float* mu   = (const float*)d_in[1];
    const float* buoy = (const float*)d_in[2];
    const float* amps = (const float*)d_in[3];
    const int*   sloc = (const int*)d_in[4];
    const int*   rloc = (const int*)d_in[5];
    float* out = (float*)d_out;

    sim_kernel<<<NBLK, TPB>>>(lamb, mu, buoy, amps, sloc, rloc, out);
}

// round 13
// speedup vs baseline: 1.8911x; 1.8911x over previous
#include <cuda_runtime.h>
#include <math.h>

#define NG     320
#define NS1    (NG*NG)
#define NSHOT  2
#define NSRC   8
#define NREC   96
#define NT     160
#define PML_W  20
#define NBLK   256          // 128 tiles x 2 shots
#define TPB    400
#define TILE_R 20
#define TILE_C 40
#define TCB    8
#define TRB    16
#define SW     45           // velocity SMEM frame stride (core+-2: 24 rows x 44)
#define SST    41           // stress SMEM frame stride (core only: 20 rows x 40)
#define IDHF   0.25f
#define DTF    4.0e-4f

// Triple-buffered global stress (outer frame only). Velocity: registers/SMEM.
__device__ float g_syy[3][NSHOT*NS1];
__device__ float g_sxy[3][NSHOT*NS1];
__device__ float g_sxx[3][NSHOT*NS1];
__device__ float g_recs[NT*NSHOT*NREC];

__device__ __align__(128) unsigned g_flag[NBLK*32];
__device__ __align__(128) unsigned g_count = 0;
__device__ __align__(128) volatile unsigned g_phase = 0;

__device__ __forceinline__ void gbar(unsigned target)
{
    __syncthreads();
    if (threadIdx.x == 0) {
        __threadfence();
        if (atomicAdd(&g_count, 1u) == NBLK - 1) {
            g_count = 0;
            __threadfence();
            g_phase = target;
        } else {
            while ((int)(g_phase - target) < 0) { }
        }
        __threadfence();
    }
    __syncthreads();
}

__device__ __forceinline__ unsigned ld_acq(const unsigned* p)
{
    unsigned v;
    asm volatile("ld.acquire.gpu.global.u32 %0, [%1];" : "=r"(v) : "l"(p) : "memory");
    return v;
}
__device__ __forceinline__ unsigned ld_acq_cta(const unsigned* p)
{
    unsigned v;
    asm volatile("ld.acquire.cta.u32 %0, [%1];" : "=r"(v) : "l"(p) : "memory");
    return v;
}
__device__ __forceinline__ void red_add(unsigned* p)
{
    asm volatile("red.global.add.u32 [%0], %1;" :: "l"(p), "r"(1u) : "memory");
}

__device__ __forceinline__ float pml_b(int i)
{
    const double d0 = 3.0 * 1600.0 * log(1000.0) / (2.0 * PML_W * 4.0);
    double dd = 0.0;
    if (i < PML_W) {
        double a = (double)(PML_W - i) / PML_W;
        dd = d0 * a * a;
    } else if (i >= NG - PML_W) {
        double a = ((double)i - (NG - 1 - PML_W)) / PML_W;
        dd = d0 * a * a;
    }
    return (float)exp(-dd * 4.0e-4);
}

__device__ __forceinline__ float2 ld2(const float* __restrict__ p, int idx)
{
    return *reinterpret_cast<const float2*>(p + idx);
}
__device__ __forceinline__ void st2(float* __restrict__ p, int idx, float a, float b)
{
    *reinterpret_cast<float2*>(p + idx) = make_float2(a, b);
}

__global__ __launch_bounds__(TPB, 2) void sim_kernel(
    const float* __restrict__ lamb,
    const float* __restrict__ mu,
    const float* __restrict__ buoy,
    const float* __restrict__ amps,   // [NSHOT, NSRC, NT]
    const int*   __restrict__ sloc,   // [NSHOT, NSRC, 2]
    const int*   __restrict__ rloc,   // [NSHOT, NREC, 2]
    float* __restrict__ out)          // [NSHOT, NREC, NT-1]
{
    __shared__ float s_vy[24*SW],  s_vx[24*SW];
    __shared__ float s_tyy[20*SST], s_txy[20*SST], s_txx[20*SST];
    __shared__ unsigned s_ready;

    const int tid  = threadIdx.x;
    const int blk  = blockIdx.x;
    const int shot = blk & 1;
    const int tile = blk >> 1;
    const int by0 = (tile / TCB) * TILE_R;
    const int bx0 = (tile % TCB) * TILE_C;
    const int rr = tid / 20;
    const int pp = tid - rr * 20;
    const int cx = 2 * pp;
    const int y  = by0 + rr;
    const int x0 = bx0 + cx;
    const int base = shot * NS1;
    const int o = y * NG + x0;
    unsigned ph = g_phase;
    const unsigned F = g_flag[blk * 32];

    // 8 pollers (interior threads): tid 168..175 -> neighbor tid-168
    const bool is_poller = (tid >= 168 && tid < 176);
    int my_nboff = 0;
    if (is_poller) {
        const int dR[8] = {-1,-1,-1, 0, 0, 1, 1, 1};
        const int dC[8] = {-1, 0, 1,-1, 1,-1, 0, 1};
        int i = tid - 168;
        int bR = tile / TCB, bC = tile % TCB;
        int nR = (bR + dR[i] + TRB) % TRB;
        int nC = (bC + dC[i] + TCB) % TCB;
        my_nboff = ((((nR * TCB + nC) << 1) | shot)) * 32;
    }

    // interior: all core stencil taps stay inside the tile
    const bool interior = (rr >= 2 && rr <= 17 && pp >= 1 && pp <= 18);

    // ---- core wrapped global indices (for boundary L2 taps) ----
    const int ym1 = (y + NG - 1) % NG, ym2 = (y + NG - 2) % NG;
    const int yp1 = (y + 1) % NG,      yp2 = (y + 2) % NG;
    const int row  = y   * NG;
    const int rym1 = ym1 * NG, rym2 = ym2 * NG;
    const int ryp1 = yp1 * NG, ryp2 = yp2 * NG;
    const int xm2c = (x0 == 0)      ? NG - 2 : x0 - 2;
    const int xp2c = (x0 == NG - 2) ? 0      : x0 + 2;

    const float byv  = pml_b(y);
    const float bxv0 = pml_b(x0);
    const float bxv1 = pml_b(x0 + 1);
    const float2 bv2  = *reinterpret_cast<const float2*>(buoy + o);
    const float2 lam2 = *reinterpret_cast<const float2*>(lamb + o);
    const float2 mu2  = *reinterpret_cast<const float2*>(mu + o);
    const float l2m0 = lam2.x + 2.0f * mu2.x;
    const float l2m1 = lam2.y + 2.0f * mu2.y;
    const bool ybord = (y < 2 || y >= NG - 2);
    const float mk0 = (ybord || x0     < 2 || x0     >= NG - 2) ? 0.0f : 1.0f;
    const float mk1 = (ybord || x0 + 1 < 2 || x0 + 1 >= NG - 2) ? 0.0f : 1.0f;
    const int svc = (rr + 2) * SW + (cx + 2);    // own cell0 in SMEM vel frame
    const int ssq = rr * SST + cx;               // own cell0 in SMEM stress frame
    // neighbors (and our boundary threads) only tap our cells within 4 of edge
    const bool do_stg = (rr < 4) || (rr >= 16) || (pp < 2) || (pp >= 18);

    unsigned smask = 0u;
#pragma unroll
    for (int s = 0; s < NSRC; s++) {
        int sy = sloc[(shot*NSRC + s)*2], sx = sloc[(shot*NSRC + s)*2 + 1];
        if (sy == y && sx == x0)     smask |= 1u << s;
        if (sy == y && sx == x0 + 1) smask |= 1u << (s + 8);
    }

    int rcode[8];
    int rcnt = 0;
    bool rovf = false;
    for (int r = 0; r < NREC; r++) {
        int e = shot * NREC + r;
        int ry = rloc[e*2], rx = rloc[e*2 + 1];
        if (ry == y && (rx == x0 || rx == x0 + 1)) {
            if (rcnt < 8) rcode[rcnt++] = e * 2 + (rx - x0);
            else rovf = true;
        }
    }

    // ---- ring: annulus 1..2 as 256 single cells on threads 0..255 ----
    const bool has_ring = (tid < 256);
    int i_o = 0, i_ym1 = 0, i_ym2 = 0, i_yp1 = 0, i_yp2 = 0;
    int i_xm1 = 0, i_xm2 = 0, i_xp1 = 0, i_xp2 = 0;
    int rvv = 0;
    float rbyv = 0, rbxv = 0, rbv = 0, rmk = 0;
    unsigned rsmask = 0u;
    if (has_ring) {
        int ty, tx;
        if (tid < 88)       { ty = -2 + tid / 44;          tx = -2 + tid % 44; }
        else if (tid < 176) { ty = 20 + (tid - 88) / 44;   tx = -2 + (tid - 88) % 44; }
        else if (tid < 216) { int j = tid - 176; ty = j / 2; tx = -2 + (j & 1); }
        else                { int j = tid - 216; ty = j / 2; tx = 40 + (j & 1); }
        int gy = (by0 + ty + NG) % NG;
        int gx = (bx0 + tx + NG) % NG;
        int gro = gy * NG;
        i_o   = base + gro + gx;
        i_ym1 = base + ((gy + NG - 1) % NG) * NG + gx;
        i_ym2 = base + ((gy + NG - 2) % NG) * NG + gx;
        i_yp1 = base + ((gy + 1) % NG) * NG + gx;
        i_yp2 = base + ((gy + 2) % NG) * NG + gx;
        i_xm1 = base + gro + (gx + NG - 1) % NG;
        i_xm2 = base + gro + (gx + NG - 2) % NG;
        i_xp1 = base + gro + (gx + 1) % NG;
        i_xp2 = base + gro + (gx + 2) % NG;
        rvv = (ty + 2) * SW + (tx + 2);
        rbyv = pml_b(gy);
        rbxv = pml_b(gx);
        rbv  = buoy[gro + gx];
        rmk  = (gy < 2 || gy >= NG-2 || gx < 2 || gx >= NG-2) ? 0.0f : 1.0f;
#pragma unroll
        for (int s = 0; s < NSRC; s++)
            if (sloc[(shot*NSRC + s)*2] == gy && sloc[(shot*NSRC + s)*2 + 1] == gx)
                rsmask |= 1u << s;
    }

    // ---- persistent register state ----
    float vy0 = 0, vy1 = 0, vx0 = 0, vx1 = 0;
    float syy0 = 0, syy1 = 0, sxy0 = 0, sxy1 = 0, sxx0 = 0, sxx1 = 0;
    float cms[8] = {0,0,0,0,0,0,0,0};
    float cmv[8] = {0,0,0,0,0,0,0,0};
    float r_vy = 0, r_vx = 0;
    float rms[4] = {0,0,0,0};

    // init: zero SMEM frames + doorbell + global stress buffer 2 core
    for (int i = tid; i < 24*SW; i += TPB) { s_vy[i] = 0.f; s_vx[i] = 0.f; }
    for (int i = tid; i < 20*SST; i += TPB) { s_tyy[i] = 0.f; s_txy[i] = 0.f; s_txx[i] = 0.f; }
    if (tid == 0) s_ready = 0u;
    st2(g_syy[2], base + o, 0.f, 0.f);
    st2(g_sxy[2], base + o, 0.f, 0.f);
    st2(g_sxx[2], base + o, 0.f, 0.f);
    __syncthreads();
    if (tid == 0) { __threadfence(); red_add(&g_flag[blk * 32]); }   // flag = F+1

    const float C1 = 1.125f;
    const float C2 = -1.0f / 24.0f;

#pragma unroll 1
    for (int t = 0; t < NT; t++) {
        const unsigned tgt = F + 1u + (unsigned)t;
        const int p = (t + 2) % 3;     // read: stress(t-1)
        const int q = t % 3;           // write: stress(t)
        const float* __restrict__ Syy = g_syy[p];
        const float* __restrict__ Sxy = g_sxy[p];
        const float* __restrict__ Sxx = g_sxx[p];

        // ---- pollers: wait for own neighbor, ring the SMEM doorbell ----
        if (is_poller) {
            while ((int)(ld_acq(g_flag + my_nboff) - tgt) < 0) { }
            __threadfence_block();
            atomicAdd(&s_ready, 1u);
        }

        // ================= velocity: core pair =================
        if (interior) {
            // all taps from block-local SMEM stress frame (no wait needed)
            float d0, d1, m;

            d0 = (C1*(syy0 - s_tyy[ssq-SST]) + C2*(s_tyy[ssq+SST]   - s_tyy[ssq-2*SST])) * IDHF;
            d1 = (C1*(syy1 - s_tyy[ssq-SST+1]) + C2*(s_tyy[ssq+SST+1] - s_tyy[ssq-2*SST+1])) * IDHF;
            m = cms[0]; m = byv*m + (byv-1.0f)*d0; cms[0] = m;
            float ay0 = d0 + m;
            m = cms[4]; m = byv*m + (byv-1.0f)*d1; cms[4] = m;
            float ay1 = d1 + m;

            d0 = (C1*(sxy1 - sxy0) + C2*(s_txy[ssq+2] - s_txy[ssq-1])) * IDHF;
            d1 = (C1*(s_txy[ssq+2] - sxy1) + C2*(s_txy[ssq+3] - sxy0)) * IDHF;
            m = cms[1]; m = bxv0*m + (bxv0-1.0f)*d0; cms[1] = m;
            ay0 += d0 + m;
            m = cms[5]; m = bxv1*m + (bxv1-1.0f)*d1; cms[5] = m;
            ay1 += d1 + m;

            vy0 += DTF * bv2.x * ay0;
            vy1 += DTF * bv2.y * ay1;

            d0 = (C1*(sxx0 - s_txx[ssq-1]) + C2*(sxx1 - s_txx[ssq-2])) * IDHF;
            d1 = (C1*(sxx1 - sxx0) + C2*(s_txx[ssq+2] - s_txx[ssq-1])) * IDHF;
            m = cms[2]; m = bxv0*m + (bxv0-1.0f)*d0; cms[2] = m;
            float ax0 = d0 + m;
            m = cms[6]; m = bxv1*m + (bxv1-1.0f)*d1; cms[6] = m;
            float ax1 = d1 + m;

            d0 = (C1*(s_txy[ssq+SST]   - sxy0) + C2*(s_txy[ssq+2*SST]   - s_txy[ssq-SST])) * IDHF;
            d1 = (C1*(s_txy[ssq+SST+1] - sxy1) + C2*(s_txy[ssq+2*SST+1] - s_txy[ssq-SST+1])) * IDHF;
            m = cms[3]; m = byv*m + (byv-1.0f)*d0; cms[3] = m;
            ax0 += d0 + m;
            m = cms[7]; m = byv*m + (byv-1.0f)*d1; cms[7] = m;
            ax1 += d1 + m;

            vx0 += DTF * bv2.x * ax0;
            vx1 += DTF * bv2.y * ax1;
        }

        // waiters: spin on the SMEM doorbell (cheap, local)
        if (!interior || has_ring) {
            const unsigned tgt8 = 8u * (unsigned)(t + 1);
            while ((int)(ld_acq_cta(&s_ready) - tgt8) < 0) { }
        }

        if (!interior) {
            // boundary core pair: taps from L2 (own published core + neighbor halo)
            float d0, d1, m;

            float2 a_ym1 = ld2(Syy, base + rym1 + x0);
            float2 a_ym2 = ld2(Syy, base + rym2 + x0);
            float2 a_yp1 = ld2(Syy, base + ryp1 + x0);
            d0 = (C1*(syy0 - a_ym1.x) + C2*(a_yp1.x - a_ym2.x)) * IDHF;
            d1 = (C1*(syy1 - a_ym1.y) + C2*(a_yp1.y - a_ym2.y)) * IDHF;
            m = cms[0]; m = byv*m + (byv-1.0f)*d0; cms[0] = m;
            float ay0 = d0 + m;
            m = cms[4]; m = byv*m + (byv-1.0f)*d1; cms[4] = m;
            float ay1 = d1 + m;

            float2 u_xm = ld2(Sxy, base + row + xm2c);
            float2 u_xp = ld2(Sxy, base + row + xp2c);
            d0 = (C1*(sxy1 - sxy0) + C2*(u_xp.x - u_xm.y)) * IDHF;
            d1 = (C1*(u_xp.x - sxy1) + C2*(u_xp.y - sxy0)) * IDHF;
            m = cms[1]; m = bxv0*m + (bxv0-1.0f)*d0; cms[1] = m;
            ay0 += d0 + m;
            m = cms[5]; m = bxv1*m + (bxv1-1.0f)*d1; cms[5] = m;
            ay1 += d1 + m;

            vy0 += DTF * bv2.x * ay0;
            vy1 += DTF * bv2.y * ay1;

            float2 w_xm = ld2(Sxx, base + row + xm2c);
            float2 w_xp = ld2(Sxx, base + row + xp2c);
            d0 = (C1*(sxx0 - w_xm.y) + C2*(sxx1 - w_xm.x)) * IDHF;
            d1 = (C1*(sxx1 - sxx0) + C2*(w_xp.x - w_xm.y)) * IDHF;
            m = cms[2]; m = bxv0*m + (bxv0-1.0f)*d0; cms[2] = m;
            float ax0 = d0 + m;
            m = cms[6]; m = bxv1*m + (bxv1-1.0f)*d1; cms[6] = m;
            float ax1 = d1 + m;

            float2 s_yp1v = ld2(Sxy, base + ryp1 + x0);
            float2 s_yp2v = ld2(Sxy, base + ryp2 + x0);
            float2 s_ym1v = ld2(Sxy, base + rym1 + x0);
            d0 = (C1*(s_yp1v.x - sxy0) + C2*(s_yp2v.x - s_ym1v.x)) * IDHF;
            d1 = (C1*(s_yp1v.y - sxy1) + C2*(s_yp2v.y - s_ym1v.y)) * IDHF;
            m = cms[3]; m = byv*m + (byv-1.0f)*d0; cms[3] = m;
            ax0 += d0 + m;
            m = cms[7]; m = byv*m + (byv-1.0f)*d1; cms[7] = m;
            ax1 += d1 + m;

            vx0 += DTF * bv2.x * ax0;
            vx1 += DTF * bv2.y * ax1;
        }

        // sources + mask + SMEM velocity store (all core threads)
        {
            if (smask) {
#pragma unroll
                for (int s = 0; s < NSRC; s++) {
                    float a = amps[(shot*NSRC + s)*NT + t];
                    if (smask & (1u << s))       vy0 += DTF * a * bv2.x;
                    if (smask & (1u << (s + 8))) vy1 += DTF * a * bv2.y;
                }
            }
            vy0 *= mk0; vy1 *= mk1;
            vx0 *= mk0; vx1 *= mk1;
            s_vy[svc]   = vy0;
            s_vy[svc+1] = vy1;
            s_vx[svc]   = vx0;
            s_vx[svc+1] = vx1;
        }

        // receivers (own registers)
        if (rovf) {
            for (int r = 0; r < NREC; r++) {
                int e = shot * NREC + r;
                int ry = rloc[e*2], rx = rloc[e*2 + 1];
                if (ry == y && (rx == x0 || rx == x0 + 1))
                    g_recs[t*(NSHOT*NREC) + e] = (rx == x0) ? vy0 : vy1;
            }
        } else {
            for (int i = 0; i < rcnt; i++) {
                int e = rcode[i] >> 1;
                g_recs[t*(NSHOT*NREC) + e] = (rcode[i] & 1) ? vy1 : vy0;
            }
        }

        // ================= velocity: ring cell (L2 taps) =================
        if (has_ring) {
            float d, m;

            d = (C1*(Syy[i_o] - Syy[i_ym1]) + C2*(Syy[i_yp1] - Syy[i_ym2])) * IDHF;
            m = rms[0]; m = rbyv*m + (rbyv-1.0f)*d; rms[0] = m;
            float ay = d + m;

            d = (C1*(Sxy[i_xp1] - Sxy[i_o]) + C2*(Sxy[i_xp2] - Sxy[i_xm1])) * IDHF;
            m = rms[1]; m = rbxv*m + (rbxv-1.0f)*d; rms[1] = m;
            ay += d + m;

            r_vy += DTF * rbv * ay;

            d = (C1*(Sxx[i_o] - Sxx[i_xm1]) + C2*(Sxx[i_xp1] - Sxx[i_xm2])) * IDHF;
            m = rms[2]; m = rbxv*m + (rbxv-1.0f)*d; rms[2] = m;
            float ax = d + m;

            d = (C1*(Sxy[i_yp1] - Sxy[i_o]) + C2*(Sxy[i_yp2] - Sxy[i_ym1])) * IDHF;
            m = rms[3]; m = rbyv*m + (rbyv-1.0f)*d; rms[3] = m;
            ax += d + m;

            r_vx += DTF * rbv * ax;

            if (rsmask) {
#pragma unroll
                for (int s = 0; s < NSRC; s++)
                    if (rsmask & (1u << s))
                        r_vy += DTF * amps[(shot*NSRC + s)*NT + t] * rbv;
            }
            r_vy *= rmk;
            r_vx *= rmk;
            s_vy[rvv] = r_vy;
            s_vx[rvv] = r_vx;
        }

        __syncthreads();   // [V] velocity frame complete; all polls ordered

        // ================= stress: core (SMEM vel taps) =================
        {
            float d0, d1, m;

            d0 = (C1*(s_vy[svc+SW]   - vy0) + C2*(s_vy[svc+2*SW]   - s_vy[svc-SW])) * IDHF;
            d1 = (C1*(s_vy[svc+SW+1] - vy1) + C2*(s_vy[svc+2*SW+1] - s_vy[svc-SW+1])) * IDHF;
            m = cmv[0]; m = byv*m + (byv-1.0f)*d0; cmv[0] = m;
            float e10 = d0 + m;
            m = cmv[4]; m = byv*m + (byv-1.0f)*d1; cmv[4] = m;
            float e11 = d1 + m;

            float vxm1 = s_vx[svc-1], vxm2 = s_vx[svc-2];
            float vxp2 = s_vx[svc+2];
            d0 = (C1*(vx0 - vxm1) + C2*(vx1 - vxm2)) * IDHF;
            d1 = (C1*(vx1 - vx0) + C2*(vxp2 - vxm1)) * IDHF;
            m = cmv[1]; m = bxv0*m + (bxv0-1.0f)*d0; cmv[1] = m;
            float e20 = d0 + m;
            m = cmv[5]; m = bxv1*m + (bxv1-1.0f)*d1; cmv[5] = m;
            float e21 = d1 + m;

            syy0 = (syy0 + DTF*(l2m0*e10 + lam2.x*e20)) * mk0;
            syy1 = (syy1 + DTF*(l2m1*e11 + lam2.y*e21)) * mk1;
            sxx0 = (sxx0 + DTF*(l2m0*e20 + lam2.x*e10)) * mk0;
            sxx1 = (sxx1 + DTF*(l2m1*e21 + lam2.y*e11)) * mk1;

            float vym1 = s_vy[svc-1];
            float vyp2 = s_vy[svc+2], vyp3 = s_vy[svc+3];
            d0 = (C1*(vy1 - vy0) + C2*(vyp2 - vym1)) * IDHF;
            d1 = (C1*(vyp2 - vy1) + C2*(vyp3 - vy0)) * IDHF;
            m = cmv[2]; m = bxv0*m + (bxv0-1.0f)*d0; cmv[2] = m;
            float g0 = d0 + m;
            m = cmv[6]; m = bxv1*m + (bxv1-1.0f)*d1; cmv[6] = m;
            float g1 = d1 + m;

            d0 = (C1*(vx0 - s_vx[svc-SW])   + C2*(s_vx[svc+SW]   - s_vx[svc-2*SW])) * IDHF;
            d1 = (C1*(vx1 - s_vx[svc-SW+1]) + C2*(s_vx[svc+SW+1] - s_vx[svc-2*SW+1])) * IDHF;
            m = cmv[3]; m = byv*m + (byv-1.0f)*d0; cmv[3] = m;
            g0 += d0 + m;
            m = cmv[7]; m = byv*m + (byv-1.0f)*d1; cmv[7] = m;
            g1 += d1 + m;

            sxy0 = (sxy0 + DTF*mu2.x*g0) * mk0;
            sxy1 = (sxy1 + DTF*mu2.y*g1) * mk1;

            // SMEM stress frame (read by interior velocity next step)
            s_tyy[ssq] = syy0; s_tyy[ssq+1] = syy1;
            s_txy[ssq] = sxy0; s_txy[ssq+1] = sxy1;
            s_txx[ssq] = sxx0; s_txx[ssq+1] = sxx1;

            if (do_stg) {
                st2(g_syy[q], base + o, syy0, syy1);
                st2(g_sxy[q], base + o, sxy0, sxy1);
                st2(g_sxx[q], base + o, sxx0, sxx1);
            }
        }

        // [S] publish step t
        __syncthreads();
        if (tid == 0) { __threadfence(); red_add(&g_flag[blk * 32]); }
    }

    // ---------------- finalize (needs all blocks' g_recs) ----------------
    gbar(ph + 1);
    const int gtid = blk * TPB + tid;
    const int total = NSHOT * NREC * (NT - 1);
    if (gtid < total) {
        int t = gtid % (NT - 1);
        int e = gtid / (NT - 1);
        out[e * (NT - 1) + t] = 0.5f * (g_recs[(t + 1)*(NSHOT*NREC) + e]
                                      + g_recs[t      *(NSHOT*NREC) + e]);
    }
}

extern "C" void kernel_launch(void* const* d_in, const int* in_sizes, int n_in,
                              void* d_out, int out_size)
{
    const float* lamb = (const float*)d_in[0];
    const float* mu   = (const float*)d_in[1];
    const float* buoy = (const float*)d_in[2];
    const float* amps = (const float*)d_in[3];
    const int*   sloc = (const int*)d_in[4];
    const int*   rloc = (const int*)d_in[5];
    float* out = (float*)d_out;

    sim_kernel<<<NBLK, TPB>>>(lamb, mu, buoy, amps, sloc, rloc, out);
}

// round 14
// speedup vs baseline: 2.5976x; 1.3736x over previous
#include <cuda_runtime.h>
#include <math.h>

#define NG     320
#define NS1    (NG*NG)
#define NSHOT  2
#define NSRC   8
#define NREC   96
#define NT     160
#define PML_W  20
#define NBLK   256          // 128 tiles x 2 shots
#define TPB    400
#define TILE_R 20
#define TILE_C 40
#define TCB    8
#define TRB    16
#define NRING  240
#define EXT_R  24
#define EXT_C  45           // velocity SMEM frame (core+-2, padded)
#define SST    41           // stress SMEM frame stride (20 rows x 40 cols)
#define IDHF   0.25f
#define DTF    4.0e-4f

// Triple-buffered global stress (outer 4-frame only). Velocity: regs/SMEM.
__device__ float g_syy[3][NSHOT*NS1];
__device__ float g_sxy[3][NSHOT*NS1];
__device__ float g_sxx[3][NSHOT*NS1];
__device__ float g_recs[NT*NSHOT*NREC];

__device__ __align__(128) unsigned g_flag[NBLK*32];
__device__ __align__(128) unsigned g_count = 0;
__device__ __align__(128) volatile unsigned g_phase = 0;

__device__ __forceinline__ void gbar(unsigned target)
{
    __syncthreads();
    if (threadIdx.x == 0) {
        __threadfence();
        if (atomicAdd(&g_count, 1u) == NBLK - 1) {
            g_count = 0;
            __threadfence();
            g_phase = target;
        } else {
            while ((int)(g_phase - target) < 0) { }
        }
        __threadfence();
    }
    __syncthreads();
}

__device__ __forceinline__ unsigned ld_acq(const unsigned* p)
{
    unsigned v;
    asm volatile("ld.acquire.gpu.global.u32 %0, [%1];" : "=r"(v) : "l"(p) : "memory");
    return v;
}
__device__ __forceinline__ void red_add(unsigned* p)
{
    asm volatile("red.global.add.u32 [%0], %1;" :: "l"(p), "r"(1u) : "memory");
}

__device__ __forceinline__ float pml_b(int i)
{
    const double d0 = 3.0 * 1600.0 * log(1000.0) / (2.0 * PML_W * 4.0);
    double dd = 0.0;
    if (i < PML_W) {
        double a = (double)(PML_W - i) / PML_W;
        dd = d0 * a * a;
    } else if (i >= NG - PML_W) {
        double a = ((double)i - (NG - 1 - PML_W)) / PML_W;
        dd = d0 * a * a;
    }
    return (float)exp(-dd * 4.0e-4);
}

__device__ __forceinline__ float2 ld2(const float* __restrict__ p, int idx)
{
    return *reinterpret_cast<const float2*>(p + idx);
}
__device__ __forceinline__ void st2(float* __restrict__ p, int idx, float a, float b)
{
    *reinterpret_cast<float2*>(p + idx) = make_float2(a, b);
}

__global__ __launch_bounds__(TPB, 2) void sim_kernel(
    const float* __restrict__ lamb,
    const float* __restrict__ mu,
    const float* __restrict__ buoy,
    const float* __restrict__ amps,   // [NSHOT, NSRC, NT]
    const int*   __restrict__ sloc,   // [NSHOT, NSRC, 2]
    const int*   __restrict__ rloc,   // [NSHOT, NREC, 2]
    float* __restrict__ out)          // [NSHOT, NREC, NT-1]
{
    __shared__ float s_vy[EXT_R][EXT_C];
    __shared__ float s_vx[EXT_R][EXT_C];
    __shared__ float s_tyy[20*SST], s_txy[20*SST], s_txx[20*SST];

    const int tid  = threadIdx.x;
    const int blk  = blockIdx.x;
    const int shot = blk & 1;
    const int tile = blk >> 1;
    const int by0 = (tile / TCB) * TILE_R;
    const int bx0 = (tile % TCB) * TILE_C;
    const int rr = tid / 20;
    const int pp = tid - rr * 20;
    const int cx = 2 * pp;
    const int y  = by0 + rr;
    const int x0 = bx0 + cx;
    const int base = shot * NS1;
    const int o = y * NG + x0;
    unsigned ph = g_phase;
    const unsigned F = g_flag[blk * 32];

    // 8 same-shot torus neighbors, polled by tid 0..7 (R7 mechanism)
    int nbid = 0;
    if (tid < 8) {
        const int dR[8] = {-1,-1,-1, 0, 0, 1, 1, 1};
        const int dC[8] = {-1, 0, 1,-1, 1,-1, 0, 1};
        int bR = tile / TCB, bC = tile % TCB;
        int nR = (bR + dR[tid] + TRB) % TRB;
        int nC = (bC + dC[tid] + TCB) % TCB;
        nbid = ((nR * TCB + nC) << 1) | shot;
    }

    // interior: all core velocity taps stay inside the tile
    const bool interior = (rr >= 2 && rr <= 17 && pp >= 1 && pp <= 18);
    // frame: cells neighbors (or their rings / our boundary threads) may read
    const bool do_stg = (rr < 4) || (rr >= 16) || (pp < 2) || (pp >= 18);

    // ---- core wrapped global indices (boundary L2 taps) ----
    const int ym1 = (y + NG - 1) % NG, ym2 = (y + NG - 2) % NG;
    const int yp1 = (y + 1) % NG,      yp2 = (y + 2) % NG;
    const int row  = y   * NG;
    const int rym1 = ym1 * NG, rym2 = ym2 * NG;
    const int ryp1 = yp1 * NG, ryp2 = yp2 * NG;
    const int xm2c = (x0 == 0)      ? NG - 2 : x0 - 2;
    const int xp2c = (x0 == NG - 2) ? 0      : x0 + 2;

    const float byv  = pml_b(y);
    const float bxv0 = pml_b(x0);
    const float bxv1 = pml_b(x0 + 1);
    const float2 bv2  = *reinterpret_cast<const float2*>(buoy + o);
    const float2 lam2 = *reinterpret_cast<const float2*>(lamb + o);
    const float2 mu2  = *reinterpret_cast<const float2*>(mu + o);
    const float l2m0 = lam2.x + 2.0f * mu2.x;
    const float l2m1 = lam2.y + 2.0f * mu2.y;
    const bool ybord = (y < 2 || y >= NG - 2);
    const float mk0 = (ybord || x0     < 2 || x0     >= NG - 2) ? 0.0f : 1.0f;
    const float mk1 = (ybord || x0 + 1 < 2 || x0 + 1 >= NG - 2) ? 0.0f : 1.0f;
    const int svc_r = 2 + rr, svc_c = 2 + cx;    // own cell0 in vel frame
    const int ssq = rr * SST + cx;               // own cell0 in stress frame

    unsigned smask = 0u;
#pragma unroll
    for (int s = 0; s < NSRC; s++) {
        int sy = sloc[(shot*NSRC + s)*2], sx = sloc[(shot*NSRC + s)*2 + 1];
        if (sy == y && sx == x0)     smask |= 1u << s;
        if (sy == y && sx == x0 + 1) smask |= 1u << (s + 8);
    }

    int rcode[8];
    int rcnt = 0;
    bool rovf = false;
    for (int r = 0; r < NREC; r++) {
        int e = shot * NREC + r;
        int ry = rloc[e*2], rx = rloc[e*2 + 1];
        if (ry == y && (rx == x0 || rx == x0 + 1)) {
            if (rcnt < 8) rcode[rcnt++] = e * 2 + (rx - x0);
            else rovf = true;
        }
    }

    // ---- ring cells (threads 0..239): cross-shaped 2-wide ring (R7) ----
    const bool has_ring = (tid < NRING);
    int r_ey = 0, r_ex = 0, r_gy = 0, r_gx = 0;
    if (has_ring) {
        int k = tid;
        if (k < 80)       { r_ey = k / 40;              r_ex = 2 + (k % 40); }
        else if (k < 160) { r_ey = 22 + (k - 80) / 40;  r_ex = 2 + ((k - 80) % 40); }
        else if (k < 200) { r_ey = 2 + (k - 160) % 20;  r_ex = (k - 160) / 20; }
        else              { r_ey = 2 + (k - 200) % 20;  r_ex = 42 + (k - 200) / 20; }
        r_gy = (by0 + r_ey - 2 + NG) % NG;
        r_gx = (bx0 + r_ex - 2 + NG) % NG;
    }
    const int gro   = r_gy * NG;
    const int grym1 = ((r_gy + NG - 1) % NG) * NG;
    const int grym2 = ((r_gy + NG - 2) % NG) * NG;
    const int gryp1 = ((r_gy + 1) % NG) * NG;
    const int gryp2 = ((r_gy + 2) % NG) * NG;
    const int gxm1 = (r_gx + NG - 1) % NG, gxm2 = (r_gx + NG - 2) % NG;
    const int gxp1 = (r_gx + 1) % NG,      gxp2 = (r_gx + 2) % NG;
    const int ro = gro + r_gx;
    const float rbyv = pml_b(r_gy);
    const float rbxv = pml_b(r_gx);
    const float rbv  = buoy[ro];
    const float rmk  = (r_gy < 2 || r_gy >= NG-2 || r_gx < 2 || r_gx >= NG-2) ? 0.0f : 1.0f;
    unsigned rsmask = 0u;
    if (has_ring) {
#pragma unroll
        for (int s = 0; s < NSRC; s++)
            if (sloc[(shot*NSRC + s)*2] == r_gy && sloc[(shot*NSRC + s)*2 + 1] == r_gx)
                rsmask |= 1u << s;
    }

    // ---- persistent register state ----
    float vy0 = 0, vy1 = 0, vx0 = 0, vx1 = 0;
    float syy0 = 0, syy1 = 0, sxy0 = 0, sxy1 = 0, sxx0 = 0, sxx1 = 0;
    float cms[8] = {0,0,0,0,0,0,0,0};
    float cmv[8] = {0,0,0,0,0,0,0,0};
    float r_vy = 0, r_vx = 0;
    float rms[4] = {0,0,0,0};

    // init: zero SMEM frames + global stress buffer 2 core
    for (int i = tid; i < EXT_R*EXT_C; i += TPB) {
        (&s_vy[0][0])[i] = 0.f;
        (&s_vx[0][0])[i] = 0.f;
    }
    for (int i = tid; i < 20*SST; i += TPB) { s_tyy[i] = 0.f; s_txy[i] = 0.f; s_txx[i] = 0.f; }
    st2(g_syy[2], base + o, 0.f, 0.f);
    st2(g_sxy[2], base + o, 0.f, 0.f);
    st2(g_sxx[2], base + o, 0.f, 0.f);
    __syncthreads();
    if (tid == 0) { __threadfence(); red_add(&g_flag[blk * 32]); }   // flag = F+1

    const float C1 = 1.125f;
    const float C2 = -1.0f / 24.0f;

#pragma unroll 1
    for (int t = 0; t < NT; t++) {
        const unsigned tgt = F + 1u + (unsigned)t;
        const int p = (t + 2) % 3;
        const int q = t % 3;
        const float* __restrict__ Syy = g_syy[p];
        const float* __restrict__ Sxy = g_sxy[p];
        const float* __restrict__ Sxx = g_sxx[p];

        // [A] 8 pollers wait for neighbors, everyone else waits at the barrier
        if (tid < 8) {
            const unsigned* fp = &g_flag[nbid * 32];
            while ((int)(ld_acq(fp) - tgt) < 0) { }
        }
        __syncthreads();

        // ================= velocity: core pair =================
        if (interior) {
            // taps from block-local SMEM stress frame (own data)
            float d0, d1, m;

            d0 = (C1*(syy0 - s_tyy[ssq-SST])   + C2*(s_tyy[ssq+SST]   - s_tyy[ssq-2*SST])) * IDHF;
            d1 = (C1*(syy1 - s_tyy[ssq-SST+1]) + C2*(s_tyy[ssq+SST+1] - s_tyy[ssq-2*SST+1])) * IDHF;
            m = cms[0]; m = byv*m + (byv-1.0f)*d0; cms[0] = m;
            float ay0 = d0 + m;
            m = cms[4]; m = byv*m + (byv-1.0f)*d1; cms[4] = m;
            float ay1 = d1 + m;

            d0 = (C1*(sxy1 - sxy0) + C2*(s_txy[ssq+2] - s_txy[ssq-1])) * IDHF;
            d1 = (C1*(s_txy[ssq+2] - sxy1) + C2*(s_txy[ssq+3] - sxy0)) * IDHF;
            m = cms[1]; m = bxv0*m + (bxv0-1.0f)*d0; cms[1] = m;
            ay0 += d0 + m;
            m = cms[5]; m = bxv1*m + (bxv1-1.0f)*d1; cms[5] = m;
            ay1 += d1 + m;

            vy0 += DTF * bv2.x * ay0;
            vy1 += DTF * bv2.y * ay1;

            d0 = (C1*(sxx0 - s_txx[ssq-1]) + C2*(sxx1 - s_txx[ssq-2])) * IDHF;
            d1 = (C1*(sxx1 - sxx0) + C2*(s_txx[ssq+2] - s_txx[ssq-1])) * IDHF;
            m = cms[2]; m = bxv0*m + (bxv0-1.0f)*d0; cms[2] = m;
            float ax0 = d0 + m;
            m = cms[6]; m = bxv1*m + (bxv1-1.0f)*d1; cms[6] = m;
            float ax1 = d1 + m;

            d0 = (C1*(s_txy[ssq+SST]   - sxy0) + C2*(s_txy[ssq+2*SST]   - s_txy[ssq-SST])) * IDHF;
            d1 = (C1*(s_txy[ssq+SST+1] - sxy1) + C2*(s_txy[ssq+2*SST+1] - s_txy[ssq-SST+1])) * IDHF;
            m = cms[3]; m = byv*m + (byv-1.0f)*d0; cms[3] = m;
            ax0 += d0 + m;
            m = cms[7]; m = byv*m + (byv-1.0f)*d1; cms[7] = m;
            ax1 += d1 + m;

            vx0 += DTF * bv2.x * ax0;
            vx1 += DTF * bv2.y * ax1;
        } else {
            // boundary: taps from L2 (neighbor halo + own published frame)
            float d0, d1, m;

            float2 a_ym1 = ld2(Syy, base + rym1 + x0);
            float2 a_ym2 = ld2(Syy, base + rym2 + x0);
            float2 a_yp1 = ld2(Syy, base + ryp1 + x0);
            d0 = (C1*(syy0 - a_ym1.x) + C2*(a_yp1.x - a_ym2.x)) * IDHF;
            d1 = (C1*(syy1 - a_ym1.y) + C2*(a_yp1.y - a_ym2.y)) * IDHF;
            m = cms[0]; m = byv*m + (byv-1.0f)*d0; cms[0] = m;
            float ay0 = d0 + m;
            m = cms[4]; m = byv*m + (byv-1.0f)*d1; cms[4] = m;
            float ay1 = d1 + m;

            float2 u_xm = ld2(Sxy, base + row + xm2c);
            float2 u_xp = ld2(Sxy, base + row + xp2c);
            d0 = (C1*(sxy1 - sxy0) + C2*(u_xp.x - u_xm.y)) * IDHF;
            d1 = (C1*(u_xp.x - sxy1) + C2*(u_xp.y - sxy0)) * IDHF;
            m = cms[1]; m = bxv0*m + (bxv0-1.0f)*d0; cms[1] = m;
            ay0 += d0 + m;
            m = cms[5]; m = bxv1*m + (bxv1-1.0f)*d1; cms[5] = m;
            ay1 += d1 + m;

            vy0 += DTF * bv2.x * ay0;
            vy1 += DTF * bv2.y * ay1;

            float2 w_xm = ld2(Sxx, base + row + xm2c);
            float2 w_xp = ld2(Sxx, base + row + xp2c);
            d0 = (C1*(sxx0 - w_xm.y) + C2*(sxx1 - w_xm.x)) * IDHF;
            d1 = (C1*(sxx1 - sxx0) + C2*(w_xp.x - w_xm.y)) * IDHF;
            m = cms[2]; m = bxv0*m + (bxv0-1.0f)*d0; cms[2] = m;
            float ax0 = d0 + m;
            m = cms[6]; m = bxv1*m + (bxv1-1.0f)*d1; cms[6] = m;
            float ax1 = d1 + m;

            float2 s_yp1v = ld2(Sxy, base + ryp1 + x0);
            float2 s_yp2v = ld2(Sxy, base + ryp2 + x0);
            float2 s_ym1v = ld2(Sxy, base + rym1 + x0);
            d0 = (C1*(s_yp1v.x - sxy0) + C2*(s_yp2v.x - s_ym1v.x)) * IDHF;
            d1 = (C1*(s_yp1v.y - sxy1) + C2*(s_yp2v.y - s_ym1v.y)) * IDHF;
            m = cms[3]; m = byv*m + (byv-1.0f)*d0; cms[3] = m;
            ax0 += d0 + m;
            m = cms[7]; m = byv*m + (byv-1.0f)*d1; cms[7] = m;
            ax1 += d1 + m;

            vx0 += DTF * bv2.x * ax0;
            vx1 += DTF * bv2.y * ax1;
        }

        // sources + mask + vel SMEM store
        {
            if (smask) {
#pragma unroll
                for (int s = 0; s < NSRC; s++) {
                    float a = amps[(shot*NSRC + s)*NT + t];
                    if (smask & (1u << s))       vy0 += DTF * a * bv2.x;
                    if (smask & (1u << (s + 8))) vy1 += DTF * a * bv2.y;
                }
            }
            vy0 *= mk0; vy1 *= mk1;
            vx0 *= mk0; vx1 *= mk1;
            s_vy[svc_r][svc_c]   = vy0;
            s_vy[svc_r][svc_c+1] = vy1;
            s_vx[svc_r][svc_c]   = vx0;
            s_vx[svc_r][svc_c+1] = vx1;
        }

        // receivers (own registers)
        if (rovf) {
            for (int r = 0; r < NREC; r++) {
                int e = shot * NREC + r;
                int ry = rloc[e*2], rx = rloc[e*2 + 1];
                if (ry == y && (rx == x0 || rx == x0 + 1))
                    g_recs[t*(NSHOT*NREC) + e] = (rx == x0) ? vy0 : vy1;
            }
        } else {
            for (int i = 0; i < rcnt; i++) {
                int e = rcode[i] >> 1;
                g_recs[t*(NSHOT*NREC) + e] = (rcode[i] & 1) ? vy1 : vy0;
            }
        }

        // ================= velocity: ring cell (L2 taps, R7) =================
        if (has_ring) {
            float d, m;

            d = (C1*(Syy[base+ro] - Syy[base+grym1+r_gx])
               + C2*(Syy[base+gryp1+r_gx] - Syy[base+grym2+r_gx])) * IDHF;
            m = rms[0]; m = rbyv*m + (rbyv-1.0f)*d; rms[0] = m;
            float ay = d + m;

            d = (C1*(Sxy[base+gro+gxp1] - Sxy[base+ro])
               + C2*(Sxy[base+gro+gxp2] - Sxy[base+gro+gxm1])) * IDHF;
            m = rms[1]; m = rbxv*m + (rbxv-1.0f)*d; rms[1] = m;
            ay += d + m;

            r_vy += DTF * rbv * ay;

            d = (C1*(Sxx[base+ro] - Sxx[base+gro+gxm1])
               + C2*(Sxx[base+gro+gxp1] - Sxx[base+gro+gxm2])) * IDHF;
            m = rms[2]; m = rbxv*m + (rbxv-1.0f)*d; rms[2] = m;
            float ax = d + m;

            d = (C1*(Sxy[base+gryp1+r_gx] - Sxy[base+ro])
               + C2*(Sxy[base+gryp2+r_gx] - Sxy[base+grym1+r_gx])) * IDHF;
            m = rms[3]; m = rbyv*m + (rbyv-1.0f)*d; rms[3] = m;
            ax += d + m;

            r_vx += DTF * rbv * ax;

            if (rsmask) {
#pragma unroll
                for (int s = 0; s < NSRC; s++)
                    if (rsmask & (1u << s))
                        r_vy += DTF * amps[(shot*NSRC + s)*NT + t] * rbv;
            }
            r_vy *= rmk;
            r_vx *= rmk;
            s_vy[r_ey][r_ex] = r_vy;
            s_vx[r_ey][r_ex] = r_vx;
        }

        __syncthreads();   // [V] velocity frame complete

        // ======== stress: FRAME cells first (neighbor-visible) ========
        if (do_stg) {
            const int sy = svc_r, sx = svc_c;
            float d0, d1, m;

            d0 = (C1*(s_vy[sy+1][sx]   - vy0) + C2*(s_vy[sy+2][sx]   - s_vy[sy-1][sx])) * IDHF;
            d1 = (C1*(s_vy[sy+1][sx+1] - vy1) + C2*(s_vy[sy+2][sx+1] - s_vy[sy-1][sx+1])) * IDHF;
            m = cmv[0]; m = byv*m + (byv-1.0f)*d0; cmv[0] = m;
            float e10 = d0 + m;
            m = cmv[4]; m = byv*m + (byv-1.0f)*d1; cmv[4] = m;
            float e11 = d1 + m;

            float vxm1 = s_vx[sy][sx-1], vxm2 = s_vx[sy][sx-2];
            float vxp2 = s_vx[sy][sx+2];
            d0 = (C1*(vx0 - vxm1) + C2*(vx1 - vxm2)) * IDHF;
            d1 = (C1*(vx1 - vx0) + C2*(vxp2 - vxm1)) * IDHF;
            m = cmv[1]; m = bxv0*m + (bxv0-1.0f)*d0; cmv[1] = m;
            float e20 = d0 + m;
            m = cmv[5]; m = bxv1*m + (bxv1-1.0f)*d1; cmv[5] = m;
            float e21 = d1 + m;

            syy0 = (syy0 + DTF*(l2m0*e10 + lam2.x*e20)) * mk0;
            syy1 = (syy1 + DTF*(l2m1*e11 + lam2.y*e21)) * mk1;
            sxx0 = (sxx0 + DTF*(l2m0*e20 + lam2.x*e10)) * mk0;
            sxx1 = (sxx1 + DTF*(l2m1*e21 + lam2.y*e11)) * mk1;

            float vym1 = s_vy[sy][sx-1];
            float vyp2 = s_vy[sy][sx+2], vyp3 = s_vy[sy][sx+3];
            d0 = (C1*(vy1 - vy0) + C2*(vyp2 - vym1)) * IDHF;
            d1 = (C1*(vyp2 - vy1) + C2*(vyp3 - vy0)) * IDHF;
            m = cmv[2]; m = bxv0*m + (bxv0-1.0f)*d0; cmv[2] = m;
            float g0 = d0 + m;
            m = cmv[6]; m = bxv1*m + (bxv1-1.0f)*d1; cmv[6] = m;
            float g1 = d1 + m;

            d0 = (C1*(vx0 - s_vx[sy-1][sx])   + C2*(s_vx[sy+1][sx]   - s_vx[sy-2][sx])) * IDHF;
            d1 = (C1*(vx1 - s_vx[sy-1][sx+1]) + C2*(s_vx[sy+1][sx+1] - s_vx[sy-2][sx+1])) * IDHF;
            m = cmv[3]; m = byv*m + (byv-1.0f)*d0; cmv[3] = m;
            g0 += d0 + m;
            m = cmv[7]; m = byv*m + (byv-1.0f)*d1; cmv[7] = m;
            g1 += d1 + m;

            sxy0 = (sxy0 + DTF*mu2.x*g0) * mk0;
            sxy1 = (sxy1 + DTF*mu2.y*g1) * mk1;

            s_tyy[ssq] = syy0; s_tyy[ssq+1] = syy1;
            s_txy[ssq] = sxy0; s_txy[ssq+1] = sxy1;
            s_txx[ssq] = sxx0; s_txx[ssq+1] = sxx1;

            st2(g_syy[q], base + o, syy0, syy1);
            st2(g_sxy[q], base + o, sxy0, sxy1);
            st2(g_sxx[q], base + o, sxx0, sxx1);
        }

        // [S] publish step t as soon as the frame is stored
        __syncthreads();
        if (tid == 0) { __threadfence(); red_add(&g_flag[blk * 32]); }

        // ======== stress: INTERIOR cells (hidden behind next poll) ========
        if (!do_stg) {
            const int sy = svc_r, sx = svc_c;
            float d0, d1, m;

            d0 = (C1*(s_vy[sy+1][sx]   - vy0) + C2*(s_vy[sy+2][sx]   - s_vy[sy-1][sx])) * IDHF;
            d1 = (C1*(s_vy[sy+1][sx+1] - vy1) + C2*(s_vy[sy+2][sx+1] - s_vy[sy-1][sx+1])) * IDHF;
            m = cmv[0]; m = byv*m + (byv-1.0f)*d0; cmv[0] = m;
            float e10 = d0 + m;
            m = cmv[4]; m = byv*m + (byv-1.0f)*d1; cmv[4] = m;
            float e11 = d1 + m;

            float vxm1 = s_vx[sy][sx-1], vxm2 = s_vx[sy][sx-2];
            float vxp2 = s_vx[sy][sx+2];
            d0 = (C1*(vx0 - vxm1) + C2*(vx1 - vxm2)) * IDHF;
            d1 = (C1*(vx1 - vx0) + C2*(vxp2 - vxm1)) * IDHF;
            m = cmv[1]; m = bxv0*m + (bxv0-1.0f)*d0; cmv[1] = m;
            float e20 = d0 + m;
            m = cmv[5]; m = bxv1*m + (bxv1-1.0f)*d1; cmv[5] = m;
            float e21 = d1 + m;

            syy0 = (syy0 + DTF*(l2m0*e10 + lam2.x*e20)) * mk0;
            syy1 = (syy1 + DTF*(l2m1*e11 + lam2.y*e21)) * mk1;
            sxx0 = (sxx0 + DTF*(l2m0*e20 + lam2.x*e10)) * mk0;
            sxx1 = (sxx1 + DTF*(l2m1*e21 + lam2.y*e11)) * mk1;

            float vym1 = s_vy[sy][sx-1];
            float vyp2 = s_vy[sy][sx+2], vyp3 = s_vy[sy][sx+3];
            d0 = (C1*(vy1 - vy0) + C2*(vyp2 - vym1)) * IDHF;
            d1 = (C1*(vyp2 - vy1) + C2*(vyp3 - vy0)) * IDHF;
            m = cmv[2]; m = bxv0*m + (bxv0-1.0f)*d0; cmv[2] = m;
            float g0 = d0 + m;
            m = cmv[6]; m = bxv1*m + (bxv1-1.0f)*d1; cmv[6] = m;
            float g1 = d1 + m;

            d0 = (C1*(vx0 - s_vx[sy-1][sx])   + C2*(s_vx[sy+1][sx]   - s_vx[sy-2][sx])) * IDHF;
            d1 = (C1*(vx1 - s_vx[sy-1][sx+1]) + C2*(s_vx[sy+1][sx+1] - s_vx[sy-2][sx+1])) * IDHF;
            m = cmv[3]; m = byv*m + (byv-1.0f)*d0; cmv[3] = m;
            g0 += d0 + m;
            m = cmv[7]; m = byv*m + (byv-1.0f)*d1; cmv[7] = m;
            g1 += d1 + m;

            sxy0 = (sxy0 + DTF*mu2.x*g0) * mk0;
            sxy1 = (sxy1 + DTF*mu2.y*g1) * mk1;

            s_tyy[ssq] = syy0; s_tyy[ssq+1] = syy1;
            s_txy[ssq] = sxy0; s_txy[ssq+1] = sxy1;
            s_txx[ssq] = sxx0; s_txx[ssq+1] = sxx1;
        }
        // next iteration's top barrier orders these STS before all reads
    }

    // ---------------- finalize (needs all blocks' g_recs) ----------------
    gbar(ph + 1);
    const int gtid = blk * TPB + tid;
    const int total = NSHOT * NREC * (NT - 1);
    if (gtid < total) {
        int t = gtid % (NT - 1);
        int e = gtid / (NT - 1);
        out[e * (NT - 1) + t] = 0.5f * (g_recs[(t + 1)*(NSHOT*NREC) + e]
                                      + g_recs[t      *(NSHOT*NREC) + e]);
    }
}

extern "C" void kernel_launch(void* const* d_in, const int* in_sizes, int n_in,
                              void* d_out, int out_size)
{
    const float* lamb = (const float*)d_in[0];
    const float* mu   = (const float*)d_in[1];
    const float* buoy = (const float*)d_in[2];
    const float* amps = (const float*)d_in[3];
    const int*   sloc = (const int*)d_in[4];
    const int*   rloc = (const int*)d_in[5];
    float* out = (float*)d_out;

    sim_kernel<<<NBLK, TPB>>>(lamb, mu, buoy, amps, sloc, rloc, out);
}

// round 15
// speedup vs baseline: 2.8099x; 1.0817x over previous
#include <cuda_runtime.h>
#include <math.h>

#define NG     320
#define NS1    (NG*NG)
#define NSHOT  2
#define NSRC   8
#define NREC   96
#define NT     160
#define PML_W  20
#define NBLK   256          // 128 tiles x 2 shots
#define TPB    416          // 13 warps: B(0-3) F2(4-6) I(7-12)
#define TILE_R 20
#define TILE_C 40
#define TCB    8
#define TRB    16
#define NRING  240
#define EXT_R  24
#define EXT_C  45           // velocity SMEM frame (core+-2, padded)
#define SST    41           // stress SMEM frame stride (20 rows x 40 cols)
#define IDHF   0.25f
#define DTF    4.0e-4f

// Triple-buffered global stress (outer 4-frame only). Velocity: regs/SMEM.
__device__ float g_syy[3][NSHOT*NS1];
__device__ float g_sxy[3][NSHOT*NS1];
__device__ float g_sxx[3][NSHOT*NS1];
__device__ float g_recs[NT*NSHOT*NREC];

__device__ __align__(128) unsigned g_flag[NBLK*32];
__device__ __align__(128) unsigned g_count = 0;
__device__ __align__(128) volatile unsigned g_phase = 0;

__device__ __forceinline__ void gbar(unsigned target)
{
    __syncthreads();
    if (threadIdx.x == 0) {
        __threadfence();
        if (atomicAdd(&g_count, 1u) == NBLK - 1) {
            g_count = 0;
            __threadfence();
            g_phase = target;
        } else {
            while ((int)(g_phase - target) < 0) { }
        }
        __threadfence();
    }
    __syncthreads();
}

__device__ __forceinline__ unsigned ld_acq(const unsigned* p)
{
    unsigned v;
    asm volatile("ld.acquire.gpu.global.u32 %0, [%1];" : "=r"(v) : "l"(p) : "memory");
    return v;
}
__device__ __forceinline__ void red_add(unsigned* p)
{
    asm volatile("red.global.add.u32 [%0], %1;" :: "l"(p), "r"(1u) : "memory");
}

__device__ __forceinline__ float pml_b(int i)
{
    const double d0 = 3.0 * 1600.0 * log(1000.0) / (2.0 * PML_W * 4.0);
    double dd = 0.0;
    if (i < PML_W) {
        double a = (double)(PML_W - i) / PML_W;
        dd = d0 * a * a;
    } else if (i >= NG - PML_W) {
        double a = ((double)i - (NG - 1 - PML_W)) / PML_W;
        dd = d0 * a * a;
    }
    return (float)exp(-dd * 4.0e-4);
}

__device__ __forceinline__ float2 ld2(const float* __restrict__ p, int idx)
{
    return *reinterpret_cast<const float2*>(p + idx);
}
__device__ __forceinline__ void st2(float* __restrict__ p, int idx, float a, float b)
{
    *reinterpret_cast<float2*>(p + idx) = make_float2(a, b);
}

__global__ __launch_bounds__(TPB, 2) void sim_kernel(
    const float* __restrict__ lamb,
    const float* __restrict__ mu,
    const float* __restrict__ buoy,
    const float* __restrict__ amps,   // [NSHOT, NSRC, NT]
    const int*   __restrict__ sloc,   // [NSHOT, NSRC, 2]
    const int*   __restrict__ rloc,   // [NSHOT, NREC, 2]
    float* __restrict__ out)          // [NSHOT, NREC, NT-1]
{
    __shared__ float s_vy[EXT_R][EXT_C];
    __shared__ float s_vx[EXT_R][EXT_C];
    __shared__ float s_tyy[20*SST], s_txy[20*SST], s_txx[20*SST];

    const int tid  = threadIdx.x;
    const int blk  = blockIdx.x;
    const int shot = blk & 1;
    const int tile = blk >> 1;
    const int by0 = (tile / TCB) * TILE_R;
    const int bx0 = (tile % TCB) * TILE_C;

    // ---- warp-pure depth-class cell mapping ----
    // B  (depth<2, velocity via L2):  tids 0..111   (warps 0..3)
    // F2 (depth 2..3, frame):         tids 128..223 (warps 4..6)
    // I  (depth>=4, interior):        tids 224..415 (warps 7..12)
    int rr = 0, pp = 0;
    bool has_core = true;
    bool vel_l2, stg;
    if (tid < 112) {
        if (tid < 80) {
            const int rtab[4] = {0, 1, 18, 19};
            rr = rtab[tid / 20];
            pp = tid % 20;
        } else {
            rr = 2 + (tid - 80) / 2;
            pp = ((tid - 80) & 1) ? 19 : 0;
        }
        vel_l2 = true; stg = true;
    } else if (tid < 128) {
        has_core = false; vel_l2 = false; stg = false;
    } else if (tid < 224) {
        int j = tid - 128;
        if (j < 72) {
            const int rtab[4] = {2, 3, 16, 17};
            rr = rtab[j / 18];
            pp = 1 + j % 18;
        } else {
            rr = 4 + (j - 72) / 2;
            pp = ((j - 72) & 1) ? 18 : 1;
        }
        vel_l2 = false; stg = true;
    } else {
        int j = tid - 224;
        rr = 4 + j / 16;
        pp = 2 + j % 16;
        vel_l2 = false; stg = false;
    }

    const int cx = 2 * pp;
    const int y  = by0 + rr;
    const int x0 = bx0 + cx;
    const int base = shot * NS1;
    const int o = y * NG + x0;
    unsigned ph = g_phase;
    const unsigned F = g_flag[blk * 32];

    // 8 same-shot torus neighbors, polled by tid 0..7
    int nbid = 0;
    if (tid < 8) {
        const int dR[8] = {-1,-1,-1, 0, 0, 1, 1, 1};
        const int dC[8] = {-1, 0, 1,-1, 1,-1, 0, 1};
        int bR = tile / TCB, bC = tile % TCB;
        int nR = (bR + dR[tid] + TRB) % TRB;
        int nC = (bC + dC[tid] + TCB) % TCB;
        nbid = ((nR * TCB + nC) << 1) | shot;
    }

    // ---- core wrapped global indices (B-class L2 taps) ----
    const int ym1 = (y + NG - 1) % NG, ym2 = (y + NG - 2) % NG;
    const int yp1 = (y + 1) % NG,      yp2 = (y + 2) % NG;
    const int row  = y   * NG;
    const int rym1 = ym1 * NG, rym2 = ym2 * NG;
    const int ryp1 = yp1 * NG, ryp2 = yp2 * NG;
    const int xm2c = (x0 == 0)      ? NG - 2 : x0 - 2;
    const int xp2c = (x0 == NG - 2) ? 0      : x0 + 2;

    const float byv  = pml_b(y);
    const float bxv0 = pml_b(x0);
    const float bxv1 = pml_b(x0 + 1);
    const float2 bv2  = *reinterpret_cast<const float2*>(buoy + o);
    const float2 lam2 = *reinterpret_cast<const float2*>(lamb + o);
    const float2 mu2  = *reinterpret_cast<const float2*>(mu + o);
    const float l2m0 = lam2.x + 2.0f * mu2.x;
    const float l2m1 = lam2.y + 2.0f * mu2.y;
    const bool ybord = (y < 2 || y >= NG - 2);
    const float mk0 = (ybord || x0     < 2 || x0     >= NG - 2) ? 0.0f : 1.0f;
    const float mk1 = (ybord || x0 + 1 < 2 || x0 + 1 >= NG - 2) ? 0.0f : 1.0f;
    const int svc_r = 2 + rr, svc_c = 2 + cx;    // own cell0 in vel frame
    const int ssq = rr * SST + cx;               // own cell0 in stress frame

    unsigned smask = 0u;
    if (has_core) {
#pragma unroll
        for (int s = 0; s < NSRC; s++) {
            int sy = sloc[(shot*NSRC + s)*2], sx = sloc[(shot*NSRC + s)*2 + 1];
            if (sy == y && sx == x0)     smask |= 1u << s;
            if (sy == y && sx == x0 + 1) smask |= 1u << (s + 8);
        }
    }

    int rcode[8];
    int rcnt = 0;
    bool rovf = false;
    if (has_core) {
        for (int r = 0; r < NREC; r++) {
            int e = shot * NREC + r;
            int ry = rloc[e*2], rx = rloc[e*2 + 1];
            if (ry == y && (rx == x0 || rx == x0 + 1)) {
                if (rcnt < 8) rcode[rcnt++] = e * 2 + (rx - x0);
                else rovf = true;
            }
        }
    }

    // ---- ring cells (threads 0..239): cross-shaped 2-wide ring ----
    const bool has_ring = (tid < NRING);
    int r_ey = 0, r_ex = 0, r_gy = 0, r_gx = 0;
    if (has_ring) {
        int k = tid;
        if (k < 80)       { r_ey = k / 40;              r_ex = 2 + (k % 40); }
        else if (k < 160) { r_ey = 22 + (k - 80) / 40;  r_ex = 2 + ((k - 80) % 40); }
        else if (k < 200) { r_ey = 2 + (k - 160) % 20;  r_ex = (k - 160) / 20; }
        else              { r_ey = 2 + (k - 200) % 20;  r_ex = 42 + (k - 200) / 20; }
        r_gy = (by0 + r_ey - 2 + NG) % NG;
        r_gx = (bx0 + r_ex - 2 + NG) % NG;
    }
    const int gro   = r_gy * NG;
    const int grym1 = ((r_gy + NG - 1) % NG) * NG;
    const int grym2 = ((r_gy + NG - 2) % NG) * NG;
    const int gryp1 = ((r_gy + 1) % NG) * NG;
    const int gryp2 = ((r_gy + 2) % NG) * NG;
    const int gxm1 = (r_gx + NG - 1) % NG, gxm2 = (r_gx + NG - 2) % NG;
    const int gxp1 = (r_gx + 1) % NG,      gxp2 = (r_gx + 2) % NG;
    const int ro = gro + r_gx;
    const float rbyv = pml_b(r_gy);
    const float rbxv = pml_b(r_gx);
    const float rbv  = buoy[ro];
    const float rmk  = (r_gy < 2 || r_gy >= NG-2 || r_gx < 2 || r_gx >= NG-2) ? 0.0f : 1.0f;
    unsigned rsmask = 0u;
    if (has_ring) {
#pragma unroll
        for (int s = 0; s < NSRC; s++)
            if (sloc[(shot*NSRC + s)*2] == r_gy && sloc[(shot*NSRC + s)*2 + 1] == r_gx)
                rsmask |= 1u << s;
    }

    // ---- persistent register state ----
    float vy0 = 0, vy1 = 0, vx0 = 0, vx1 = 0;
    float syy0 = 0, syy1 = 0, sxy0 = 0, sxy1 = 0, sxx0 = 0, sxx1 = 0;
    float cms[8] = {0,0,0,0,0,0,0,0};
    float cmv[8] = {0,0,0,0,0,0,0,0};
    float r_vy = 0, r_vx = 0;
    float rms[4] = {0,0,0,0};

    // init: zero SMEM frames + global stress buffer 2 core
    for (int i = tid; i < EXT_R*EXT_C; i += TPB) {
        (&s_vy[0][0])[i] = 0.f;
        (&s_vx[0][0])[i] = 0.f;
    }
    for (int i = tid; i < 20*SST; i += TPB) { s_tyy[i] = 0.f; s_txy[i] = 0.f; s_txx[i] = 0.f; }
    if (has_core) {
        st2(g_syy[2], base + o, 0.f, 0.f);
        st2(g_sxy[2], base + o, 0.f, 0.f);
        st2(g_sxx[2], base + o, 0.f, 0.f);
    }
    __syncthreads();
    if (tid == 0) { __threadfence(); red_add(&g_flag[blk * 32]); }   // flag = F+1

    const float C1 = 1.125f;
    const float C2 = -1.0f / 24.0f;

#pragma unroll 1
    for (int t = 0; t < NT; t++) {
        const unsigned tgt = F + 1u + (unsigned)t;
        const int p = (t + 2) % 3;
        const int q = t % 3;
        const float* __restrict__ Syy = g_syy[p];
        const float* __restrict__ Sxy = g_sxy[p];
        const float* __restrict__ Sxx = g_sxx[p];

        // [A] 8 pollers wait for neighbors; block barrier
        if (tid < 8) {
            const unsigned* fp = &g_flag[nbid * 32];
            while ((int)(ld_acq(fp) - tgt) < 0) { }
        }
        __syncthreads();

        // ================= velocity: core pair =================
        if (has_core) {
            if (!vel_l2) {
                // F2/I warps: taps from block-local SMEM stress frame
                float d0, d1, m;

                d0 = (C1*(syy0 - s_tyy[ssq-SST])   + C2*(s_tyy[ssq+SST]   - s_tyy[ssq-2*SST])) * IDHF;
                d1 = (C1*(syy1 - s_tyy[ssq-SST+1]) + C2*(s_tyy[ssq+SST+1] - s_tyy[ssq-2*SST+1])) * IDHF;
                m = cms[0]; m = byv*m + (byv-1.0f)*d0; cms[0] = m;
                float ay0 = d0 + m;
                m = cms[4]; m = byv*m + (byv-1.0f)*d1; cms[4] = m;
                float ay1 = d1 + m;

                d0 = (C1*(sxy1 - sxy0) + C2*(s_txy[ssq+2] - s_txy[ssq-1])) * IDHF;
                d1 = (C1*(s_txy[ssq+2] - sxy1) + C2*(s_txy[ssq+3] - sxy0)) * IDHF;
                m = cms[1]; m = bxv0*m + (bxv0-1.0f)*d0; cms[1] = m;
                ay0 += d0 + m;
                m = cms[5]; m = bxv1*m + (bxv1-1.0f)*d1; cms[5] = m;
                ay1 += d1 + m;

                vy0 += DTF * bv2.x * ay0;
                vy1 += DTF * bv2.y * ay1;

                d0 = (C1*(sxx0 - s_txx[ssq-1]) + C2*(sxx1 - s_txx[ssq-2])) * IDHF;
                d1 = (C1*(sxx1 - sxx0) + C2*(s_txx[ssq+2] - s_txx[ssq-1])) * IDHF;
                m = cms[2]; m = bxv0*m + (bxv0-1.0f)*d0; cms[2] = m;
                float ax0 = d0 + m;
                m = cms[6]; m = bxv1*m + (bxv1-1.0f)*d1; cms[6] = m;
                float ax1 = d1 + m;

                d0 = (C1*(s_txy[ssq+SST]   - sxy0) + C2*(s_txy[ssq+2*SST]   - s_txy[ssq-SST])) * IDHF;
                d1 = (C1*(s_txy[ssq+SST+1] - sxy1) + C2*(s_txy[ssq+2*SST+1] - s_txy[ssq-SST+1])) * IDHF;
                m = cms[3]; m = byv*m + (byv-1.0f)*d0; cms[3] = m;
                ax0 += d0 + m;
                m = cms[7]; m = byv*m + (byv-1.0f)*d1; cms[7] = m;
                ax1 += d1 + m;

                vx0 += DTF * bv2.x * ax0;
                vx1 += DTF * bv2.y * ax1;
            } else {
                // B warps: taps from L2 (neighbor halo + own frame)
                float d0, d1, m;

                float2 a_ym1 = ld2(Syy, base + rym1 + x0);
                float2 a_ym2 = ld2(Syy, base + rym2 + x0);
                float2 a_yp1 = ld2(Syy, base + ryp1 + x0);
                d0 = (C1*(syy0 - a_ym1.x) + C2*(a_yp1.x - a_ym2.x)) * IDHF;
                d1 = (C1*(syy1 - a_ym1.y) + C2*(a_yp1.y - a_ym2.y)) * IDHF;
                m = cms[0]; m = byv*m + (byv-1.0f)*d0; cms[0] = m;
                float ay0 = d0 + m;
                m = cms[4]; m = byv*m + (byv-1.0f)*d1; cms[4] = m;
                float ay1 = d1 + m;

                float2 u_xm = ld2(Sxy, base + row + xm2c);
                float2 u_xp = ld2(Sxy, base + row + xp2c);
                d0 = (C1*(sxy1 - sxy0) + C2*(u_xp.x - u_xm.y)) * IDHF;
                d1 = (C1*(u_xp.x - sxy1) + C2*(u_xp.y - sxy0)) * IDHF;
                m = cms[1]; m = bxv0*m + (bxv0-1.0f)*d0; cms[1] = m;
                ay0 += d0 + m;
                m = cms[5]; m = bxv1*m + (bxv1-1.0f)*d1; cms[5] = m;
                ay1 += d1 + m;

                vy0 += DTF * bv2.x * ay0;
                vy1 += DTF * bv2.y * ay1;

                float2 w_xm = ld2(Sxx, base + row + xm2c);
                float2 w_xp = ld2(Sxx, base + row + xp2c);
                d0 = (C1*(sxx0 - w_xm.y) + C2*(sxx1 - w_xm.x)) * IDHF;
                d1 = (C1*(sxx1 - sxx0) + C2*(w_xp.x - w_xm.y)) * IDHF;
                m = cms[2]; m = bxv0*m + (bxv0-1.0f)*d0; cms[2] = m;
                float ax0 = d0 + m;
                m = cms[6]; m = bxv1*m + (bxv1-1.0f)*d1; cms[6] = m;
                float ax1 = d1 + m;

                float2 s_yp1v = ld2(Sxy, base + ryp1 + x0);
                float2 s_yp2v = ld2(Sxy, base + ryp2 + x0);
                float2 s_ym1v = ld2(Sxy, base + rym1 + x0);
                d0 = (C1*(s_yp1v.x - sxy0) + C2*(s_yp2v.x - s_ym1v.x)) * IDHF;
                d1 = (C1*(s_yp1v.y - sxy1) + C2*(s_yp2v.y - s_ym1v.y)) * IDHF;
                m = cms[3]; m = byv*m + (byv-1.0f)*d0; cms[3] = m;
                ax0 += d0 + m;
                m = cms[7]; m = byv*m + (byv-1.0f)*d1; cms[7] = m;
                ax1 += d1 + m;

                vx0 += DTF * bv2.x * ax0;
                vx1 += DTF * bv2.y * ax1;
            }

            // sources + mask + vel SMEM store
            if (smask) {
#pragma unroll
                for (int s = 0; s < NSRC; s++) {
                    float a = amps[(shot*NSRC + s)*NT + t];
                    if (smask & (1u << s))       vy0 += DTF * a * bv2.x;
                    if (smask & (1u << (s + 8))) vy1 += DTF * a * bv2.y;
                }
            }
            vy0 *= mk0; vy1 *= mk1;
            vx0 *= mk0; vx1 *= mk1;
            s_vy[svc_r][svc_c]   = vy0;
            s_vy[svc_r][svc_c+1] = vy1;
            s_vx[svc_r][svc_c]   = vx0;
            s_vx[svc_r][svc_c+1] = vx1;

            // receivers (own registers)
            if (rovf) {
                for (int r = 0; r < NREC; r++) {
                    int e = shot * NREC + r;
                    int ry = rloc[e*2], rx = rloc[e*2 + 1];
                    if (ry == y && (rx == x0 || rx == x0 + 1))
                        g_recs[t*(NSHOT*NREC) + e] = (rx == x0) ? vy0 : vy1;
                }
            } else {
                for (int i = 0; i < rcnt; i++) {
                    int e = rcode[i] >> 1;
                    g_recs[t*(NSHOT*NREC) + e] = (rcode[i] & 1) ? vy1 : vy0;
                }
            }
        }

        // ================= velocity: ring cell (L2 taps) =================
        if (has_ring) {
            float d, m;

            d = (C1*(Syy[base+ro] - Syy[base+grym1+r_gx])
               + C2*(Syy[base+gryp1+r_gx] - Syy[base+grym2+r_gx])) * IDHF;
            m = rms[0]; m = rbyv*m + (rbyv-1.0f)*d; rms[0] = m;
            float ay = d + m;

            d = (C1*(Sxy[base+gro+gxp1] - Sxy[base+ro])
               + C2*(Sxy[base+gro+gxp2] - Sxy[base+gro+gxm1])) * IDHF;
            m = rms[1]; m = rbxv*m + (rbxv-1.0f)*d; rms[1] = m;
            ay += d + m;

            r_vy += DTF * rbv * ay;

            d = (C1*(Sxx[base+ro] - Sxx[base+gro+gxm1])
               + C2*(Sxx[base+gro+gxp1] - Sxx[base+gro+gxm2])) * IDHF;
            m = rms[2]; m = rbxv*m + (rbxv-1.0f)*d; rms[2] = m;
            float ax = d + m;

            d = (C1*(Sxy[base+gryp1+r_gx] - Sxy[base+ro])
               + C2*(Sxy[base+gryp2+r_gx] - Sxy[base+grym1+r_gx])) * IDHF;
            m = rms[3]; m = rbyv*m + (rbyv-1.0f)*d; rms[3] = m;
            ax += d + m;

            r_vx += DTF * rbv * ax;

            if (rsmask) {
#pragma unroll
                for (int s = 0; s < NSRC; s++)
                    if (rsmask & (1u << s))
                        r_vy += DTF * amps[(shot*NSRC + s)*NT + t] * rbv;
            }
            r_vy *= rmk;
            r_vx *= rmk;
            s_vy[r_ey][r_ex] = r_vy;
            s_vx[r_ey][r_ex] = r_vx;
        }

        __syncthreads();   // [V] velocity frame complete

        // ======== stress: FRAME cells (B + F2 warps, neighbor-visible) ========
        if (has_core && stg) {
            const int sy = svc_r, sx = svc_c;
            float d0, d1, m;

            d0 = (C1*(s_vy[sy+1][sx]   - vy0) + C2*(s_vy[sy+2][sx]   - s_vy[sy-1][sx])) * IDHF;
            d1 = (C1*(s_vy[sy+1][sx+1] - vy1) + C2*(s_vy[sy+2][sx+1] - s_vy[sy-1][sx+1])) * IDHF;
            m = cmv[0]; m = byv*m + (byv-1.0f)*d0; cmv[0] = m;
            float e10 = d0 + m;
            m = cmv[4]; m = byv*m + (byv-1.0f)*d1; cmv[4] = m;
            float e11 = d1 + m;

            float vxm1 = s_vx[sy][sx-1], vxm2 = s_vx[sy][sx-2];
            float vxp2 = s_vx[sy][sx+2];
            d0 = (C1*(vx0 - vxm1) + C2*(vx1 - vxm2)) * IDHF;
            d1 = (C1*(vx1 - vx0) + C2*(vxp2 - vxm1)) * IDHF;
            m = cmv[1]; m = bxv0*m + (bxv0-1.0f)*d0; cmv[1] = m;
            float e20 = d0 + m;
            m = cmv[5]; m = bxv1*m + (bxv1-1.0f)*d1; cmv[5] = m;
            float e21 = d1 + m;

            syy0 = (syy0 + DTF*(l2m0*e10 + lam2.x*e20)) * mk0;
            syy1 = (syy1 + DTF*(l2m1*e11 + lam2.y*e21)) * mk1;
            sxx0 = (sxx0 + DTF*(l2m0*e20 + lam2.x*e10)) * mk0;
            sxx1 = (sxx1 + DTF*(l2m1*e21 + lam2.y*e11)) * mk1;

            float vym1 = s_vy[sy][sx-1];
            float vyp2 = s_vy[sy][sx+2], vyp3 = s_vy[sy][sx+3];
            d0 = (C1*(vy1 - vy0) + C2*(vyp2 - vym1)) * IDHF;
            d1 = (C1*(vyp2 - vy1) + C2*(vyp3 - vy0)) * IDHF;
            m = cmv[2]; m = bxv0*m + (bxv0-1.0f)*d0; cmv[2] = m;
            float g0 = d0 + m;
            m = cmv[6]; m = bxv1*m + (bxv1-1.0f)*d1; cmv[6] = m;
            float g1 = d1 + m;

            d0 = (C1*(vx0 - s_vx[sy-1][sx])   + C2*(s_vx[sy+1][sx]   - s_vx[sy-2][sx])) * IDHF;
            d1 = (C1*(vx1 - s_vx[sy-1][sx+1]) + C2*(s_vx[sy+1][sx+1] - s_vx[sy-2][sx+1])) * IDHF;
            m = cmv[3]; m = byv*m + (byv-1.0f)*d0; cmv[3] = m;
            g0 += d0 + m;
            m = cmv[7]; m = byv*m + (byv-1.0f)*d1; cmv[7] = m;
            g1 += d1 + m;

            sxy0 = (sxy0 + DTF*mu2.x*g0) * mk0;
            sxy1 = (sxy1 + DTF*mu2.y*g1) * mk1;

            s_tyy[ssq] = syy0; s_tyy[ssq+1] = syy1;
            s_txy[ssq] = sxy0; s_txy[ssq+1] = sxy1;
            s_txx[ssq] = sxx0; s_txx[ssq+1] = sxx1;

            st2(g_syy[q], base + o, syy0, syy1);
            st2(g_sxy[q], base + o, sxy0, sxy1);
            st2(g_sxx[q], base + o, sxx0, sxx1);
        }

        // [S] publish step t as soon as the frame is stored
        __syncthreads();
        if (tid == 0) { __threadfence(); red_add(&g_flag[blk * 32]); }

        // ======== stress: INTERIOR cells (I warps; hidden behind next poll) ========
        if (has_core && !stg) {
            const int sy = svc_r, sx = svc_c;
            float d0, d1, m;

            d0 = (C1*(s_vy[sy+1][sx]   - vy0) + C2*(s_vy[sy+2][sx]   - s_vy[sy-1][sx])) * IDHF;
            d1 = (C1*(s_vy[sy+1][sx+1] - vy1) + C2*(s_vy[sy+2][sx+1] - s_vy[sy-1][sx+1])) * IDHF;
            m = cmv[0]; m = byv*m + (byv-1.0f)*d0; cmv[0] = m;
            float e10 = d0 + m;
            m = cmv[4]; m = byv*m + (byv-1.0f)*d1; cmv[4] = m;
            float e11 = d1 + m;

            float vxm1 = s_vx[sy][sx-1], vxm2 = s_vx[sy][sx-2];
            float vxp2 = s_vx[sy][sx+2];
            d0 = (C1*(vx0 - vxm1) + C2*(vx1 - vxm2)) * IDHF;
            d1 = (C1*(vx1 - vx0) + C2*(vxp2 - vxm1)) * IDHF;
            m = cmv[1]; m = bxv0*m + (bxv0-1.0f)*d0; cmv[1] = m;
            float e20 = d0 + m;
            m = cmv[5]; m = bxv1*m + (bxv1-1.0f)*d1; cmv[5] = m;
            float e21 = d1 + m;

            syy0 = (syy0 + DTF*(l2m0*e10 + lam2.x*e20)) * mk0;
            syy1 = (syy1 + DTF*(l2m1*e11 + lam2.y*e21)) * mk1;
            sxx0 = (sxx0 + DTF*(l2m0*e20 + lam2.x*e10)) * mk0;
            sxx1 = (sxx1 + DTF*(l2m1*e21 + lam2.y*e11)) * mk1;

            float vym1 = s_vy[sy][sx-1];
            float vyp2 = s_vy[sy][sx+2], vyp3 = s_vy[sy][sx+3];
            d0 = (C1*(vy1 - vy0) + C2*(vyp2 - vym1)) * IDHF;
            d1 = (C1*(vyp2 - vy1) + C2*(vyp3 - vy0)) * IDHF;
            m = cmv[2]; m = bxv0*m + (bxv0-1.0f)*d0; cmv[2] = m;
            float g0 = d0 + m;
            m = cmv[6]; m = bxv1*m + (bxv1-1.0f)*d1; cmv[6] = m;
            float g1 = d1 + m;

            d0 = (C1*(vx0 - s_vx[sy-1][sx])   + C2*(s_vx[sy+1][sx]   - s_vx[sy-2][sx])) * IDHF;
            d1 = (C1*(vx1 - s_vx[sy-1][sx+1]) + C2*(s_vx[sy+1][sx+1] - s_vx[sy-2][sx+1])) * IDHF;
            m = cmv[3]; m = byv*m + (byv-1.0f)*d0; cmv[3] = m;
            g0 += d0 + m;
            m = cmv[7]; m = byv*m + (byv-1.0f)*d1; cmv[7] = m;
            g1 += d1 + m;

            sxy0 = (sxy0 + DTF*mu2.x*g0) * mk0;
            sxy1 = (sxy1 + DTF*mu2.y*g1) * mk1;

            s_tyy[ssq] = syy0; s_tyy[ssq+1] = syy1;
            s_txy[ssq] = sxy0; s_txy[ssq+1] = sxy1;
            s_txx[ssq] = sxx0; s_txx[ssq+1] = sxx1;
        }
        // next iteration's [A] barrier orders these STS before all reads
    }

    // ---------------- finalize (needs all blocks' g_recs) ----------------
    gbar(ph + 1);
    const int gtid = blk * TPB + tid;
    const int total = NSHOT * NREC * (NT - 1);
    if (gtid < total) {
        int t = gtid % (NT - 1);
        int e = gtid / (NT - 1);
        out[e * (NT - 1) + t] = 0.5f * (g_recs[(t + 1)*(NSHOT*NREC) + e]
                                      + g_recs[t      *(NSHOT*NREC) + e]);
    }
}

extern "C" void kernel_launch(void* const* d_in, const int* in_sizes, int n_in,
                              void* d_out, int out_size)
{
    const float* lamb = (const float*)d_in[0];
    const float* mu   = (const float*)d_in[1];
    const float* buoy = (const float*)d_in[2];
    const float* amps = (const float*)d_in[3];
    const int*   sloc = (const int*)d_in[4];
    const int*   rloc = (const int*)d_in[5];
    float* out = (float*)d_out;

    sim_kernel<<<NBLK, TPB>>>(lamb, mu, buoy, amps, sloc, rloc, out);
}